// round 5
// baseline (speedup 1.0000x reference)
#include <cuda_runtime.h>
#include <cuda_bf16.h>
#include <cstdint>
#include <cstddef>

// ------------------- problem constants -------------------
#define HD    2048        // hidden dim H
#define KTOT  14336       // 8192 + 4096 + 1024 + 1024
#define NR    8192        // rows of x / output
#define LN_EPS 1e-5f

// ------------------- GEMM tiling -------------------
#define STAGES      3
#define CHUNK_K     64                        // bf16 elems per chunk (128 B rows)
#define TILE_B      (128 * 128)               // one 128-row x 64-bf16 tile = 16 KB
#define STAGE_B     (4 * TILE_B)              // Ah, Al, Bh, Bl = 64 KB
#define SMEM_REQ    (STAGES * STAGE_B)        // 192 KB

#define SWZ128(off) ((off) ^ (((off) >> 3) & 0x70))

// ------------------- device scratch (no allocs allowed) -------------------
__device__ __nv_bfloat16 g_Ah[(size_t)HD * KTOT];   // concat D, hi plane  [2048 x 14336]
__device__ __nv_bfloat16 g_Al[(size_t)HD * KTOT];
__device__ __nv_bfloat16 g_Bh[(size_t)HD * KTOT];   // (W*scale)^T planes  [2048 x 14336]
__device__ __nv_bfloat16 g_Bl[(size_t)HD * KTOT];
__device__ __nv_bfloat16 g_xh[(size_t)NR * HD];     // x planes            [8192 x 2048]
__device__ __nv_bfloat16 g_xl[(size_t)NR * HD];
__device__ __nv_bfloat16 g_Mh[(size_t)HD * HD];     // M planes            [2048 x 2048]
__device__ __nv_bfloat16 g_Ml[(size_t)HD * HD];
__device__ float         g_h [(size_t)NR * HD];     // pre-LN activations

// ------------------- PTX helpers -------------------
__device__ __forceinline__ uint32_t smem_u32(const void* p) {
    uint32_t a;
    asm("{ .reg .u64 t; cvta.to.shared.u64 t, %1; cvt.u32.u64 %0, t; }" : "=r"(a) : "l"(p));
    return a;
}

__device__ __forceinline__ void cp_async16(uint32_t saddr, const void* gaddr) {
    asm volatile("cp.async.cg.shared.global [%0], [%1], 16;" :: "r"(saddr), "l"(gaddr));
}

__device__ __forceinline__ void ldsm4(uint32_t* r, uint32_t addr) {
    asm volatile("ldmatrix.sync.aligned.m8n8.x4.shared.b16 {%0,%1,%2,%3}, [%4];"
                 : "=r"(r[0]), "=r"(r[1]), "=r"(r[2]), "=r"(r[3]) : "r"(addr));
}

__device__ __forceinline__ void mma_bf16(float* c, const uint32_t* a, const uint32_t* b) {
    asm volatile(
        "mma.sync.aligned.m16n8k16.row.col.f32.bf16.bf16.f32 "
        "{%0,%1,%2,%3}, {%4,%5,%6,%7}, {%8,%9}, {%0,%1,%2,%3};"
        : "+f"(c[0]), "+f"(c[1]), "+f"(c[2]), "+f"(c[3])
        : "r"(a[0]), "r"(a[1]), "r"(a[2]), "r"(a[3]), "r"(b[0]), "r"(b[1]));
}

// ------------------- prep kernels -------------------

// split x into hi/lo bf16 planes
__global__ void split_x_kernel(const float* __restrict__ src) {
    size_t i = (size_t)blockIdx.x * blockDim.x + threadIdx.x;
    float v = src[i];
    __nv_bfloat16 hi = __float2bfloat16(v);
    g_xh[i] = hi;
    g_xl[i] = __float2bfloat16(v - __bfloat162float(hi));
}

// split a D matrix [HD, P] into the concat A planes at column offset colbase
__global__ void splitcat_kernel(const float* __restrict__ src, int pshift, int colbase) {
    size_t i = (size_t)blockIdx.x * blockDim.x + threadIdx.x;
    int P = 1 << pshift;
    size_t j = i >> pshift;
    int    p = (int)(i & (size_t)(P - 1));
    float v = src[i];
    __nv_bfloat16 hi = __float2bfloat16(v);
    size_t o = j * KTOT + colbase + p;
    g_Ah[o] = hi;
    g_Al[o] = __float2bfloat16(v - __bfloat162float(hi));
}

// transpose + block-scale a W matrix [P, HD] into B planes [HD, KTOT] at col offset colbase
__global__ void wtrans_kernel(const float* __restrict__ W, const float* __restrict__ S,
                              int colbase) {
    __shared__ float t[32][33];
    int n0 = blockIdx.x * 32;
    int p0 = blockIdx.y * 32;
    int tx = threadIdx.x, ty = threadIdx.y;       // block (32, 8)
    float sc = S[(p0 >> 7) * (HD >> 7) + (n0 >> 7)];
    #pragma unroll
    for (int r = 0; r < 4; ++r)
        t[ty + r * 8][tx] = W[(size_t)(p0 + ty + r * 8) * HD + n0 + tx];
    __syncthreads();
    #pragma unroll
    for (int r = 0; r < 4; ++r) {
        int n = n0 + ty + r * 8;
        int p = p0 + tx;
        float v = t[tx][ty + r * 8] * sc;
        __nv_bfloat16 hi = __float2bfloat16(v);
        size_t o = (size_t)n * KTOT + colbase + p;
        g_Bh[o] = hi;
        g_Bl[o] = __float2bfloat16(v - __bfloat162float(hi));
    }
}

// ------------------- main GEMM (split-bf16, 3 passes, mma.sync) -------------------
// mode 0:  M = A . B^T over K=KTOT, write bf16 hi/lo planes g_Mh/g_Ml
// mode 1:  h = x . M^T over K=HD,   write fp32 g_h
__global__ void __launch_bounds__(256, 1) gemm_kernel(int mode) {
    const __nv_bfloat16 *Ah, *Al, *Bh, *Bl;
    int K;
    if (mode == 0) { Ah = g_Ah; Al = g_Al; Bh = g_Bh; Bl = g_Bl; K = KTOT; }
    else           { Ah = g_xh; Al = g_xl; Bh = g_Mh; Bl = g_Ml; K = HD;   }

    extern __shared__ __align__(1024) char smem[];
    const uint32_t sb = smem_u32(smem);

    const int tid = threadIdx.x;
    const int wid = tid >> 5;
    const int lid = tid & 31;
    const int m0 = blockIdx.y * 128;   // output rows  (A rows)
    const int n0 = blockIdx.x * 128;   // output cols  (B rows)
    const int wm = (wid & 1) * 64;     // warp row offset in tile
    const int wn = (wid >> 1) * 32;    // warp col offset in tile

    const int NC = K / CHUNK_K;

    // ---- chunk loader: 16 x cp.async(16B) per thread ----
    auto load_chunk = [&](int c, int s) {
        const int k0 = c * CHUNK_K;
        const uint32_t stage = sb + s * STAGE_B;
        #pragma unroll
        for (int i = 0; i < 4; ++i) {
            int idx = tid + i * 256;           // 0..1023
            int row = idx >> 3;                // 0..127
            int seg = idx & 7;                 // 16B segment
            uint32_t sw = SWZ128((uint32_t)(row * 128 + seg * 16));
            size_t aoff = (size_t)(m0 + row) * K + k0 + seg * 8;
            size_t boff = (size_t)(n0 + row) * K + k0 + seg * 8;
            cp_async16(stage + sw,              Ah + aoff);
            cp_async16(stage + TILE_B + sw,     Al + aoff);
            cp_async16(stage + 2 * TILE_B + sw, Bh + boff);
            cp_async16(stage + 3 * TILE_B + sw, Bl + boff);
        }
        asm volatile("cp.async.commit_group;" ::: "memory");
    };

    // prologue: stages 0, 1
    load_chunk(0, 0);
    load_chunk(1, 1);

    float acc[4][4][4];
    #pragma unroll
    for (int i = 0; i < 4; ++i)
        #pragma unroll
        for (int j = 0; j < 4; ++j)
            #pragma unroll
            for (int q = 0; q < 4; ++q) acc[i][j][q] = 0.f;

    // ldmatrix address pattern bits (per lane)
    const int lrow = lid & 7;          // row within 8x8 matrix
    const int lmat = lid >> 3;         // which of the 4 matrices

    for (int c = 0; c < NC; ++c) {
        if (c == NC - 1) asm volatile("cp.async.wait_group 0;" ::: "memory");
        else             asm volatile("cp.async.wait_group 1;" ::: "memory");
        __syncthreads();

        const uint32_t stage = sb + (c % STAGES) * STAGE_B;
        const uint32_t tAh = stage;
        const uint32_t tAl = stage + TILE_B;
        const uint32_t tBh = stage + 2 * TILE_B;
        const uint32_t tBl = stage + 3 * TILE_B;

        #pragma unroll
        for (int ks = 0; ks < 4; ++ks) {
            const int kb = ks * 32;    // byte offset of this k16 step

            // B fragments: x4 covers 2 n-tiles (mats: (j0,o0),(j0,o1),(j1,o0),(j1,o1))
            uint32_t bh[4][2], bl[4][2];
            #pragma unroll
            for (int jp = 0; jp < 2; ++jp) {
                int brow = wn + jp * 16 + ((lmat >> 1) ? 8 : 0) + lrow;
                int bcol = kb + ((lmat & 1) ? 16 : 0);
                uint32_t ad = SWZ128((uint32_t)(brow * 128 + bcol));
                uint32_t r[4];
                ldsm4(r, tBh + ad);
                bh[jp * 2 + 0][0] = r[0]; bh[jp * 2 + 0][1] = r[1];
                bh[jp * 2 + 1][0] = r[2]; bh[jp * 2 + 1][1] = r[3];
                ldsm4(r, tBl + ad);
                bl[jp * 2 + 0][0] = r[0]; bl[jp * 2 + 0][1] = r[1];
                bl[jp * 2 + 1][0] = r[2]; bl[jp * 2 + 1][1] = r[3];
            }

            // A address (same pattern for both planes)
            uint32_t aad[4];
            #pragma unroll
            for (int i = 0; i < 4; ++i) {
                int arow = wm + i * 16 + ((lmat & 1) ? 8 : 0) + lrow;
                int acol = kb + ((lmat & 2) ? 16 : 0);
                aad[i] = SWZ128((uint32_t)(arow * 128 + acol));
            }

            // pass 1+2: Ah*Bh, Ah*Bl
            uint32_t af[4][4];
            #pragma unroll
            for (int i = 0; i < 4; ++i) ldsm4(af[i], tAh + aad[i]);
            #pragma unroll
            for (int i = 0; i < 4; ++i)
                #pragma unroll
                for (int j = 0; j < 4; ++j) {
                    mma_bf16(acc[i][j], af[i], bh[j]);
                    mma_bf16(acc[i][j], af[i], bl[j]);
                }
            // pass 3: Al*Bh
            #pragma unroll
            for (int i = 0; i < 4; ++i) ldsm4(af[i], tAl + aad[i]);
            #pragma unroll
            for (int i = 0; i < 4; ++i)
                #pragma unroll
                for (int j = 0; j < 4; ++j)
                    mma_bf16(acc[i][j], af[i], bh[j]);
        }

        if (c + 2 < NC) load_chunk(c + 2, (c + 2) % STAGES);
    }

    // ---- epilogue: write accumulators ----
    const int g = lid >> 2;            // row group in fragment
    const int t4 = lid & 3;            // col pair
    #pragma unroll
    for (int i = 0; i < 4; ++i) {
        #pragma unroll
        for (int j = 0; j < 4; ++j) {
            int row = m0 + wm + i * 16 + g;
            int col = n0 + wn + j * 8 + 2 * t4;
            if (mode == 1) {
                float2 v0 = make_float2(acc[i][j][0], acc[i][j][1]);
                float2 v1 = make_float2(acc[i][j][2], acc[i][j][3]);
                *reinterpret_cast<float2*>(g_h + (size_t)row * HD + col) = v0;
                *reinterpret_cast<float2*>(g_h + (size_t)(row + 8) * HD + col) = v1;
            } else {
                #pragma unroll
                for (int h = 0; h < 2; ++h) {
                    int rr = row + h * 8;
                    float f0 = acc[i][j][2 * h], f1 = acc[i][j][2 * h + 1];
                    __nv_bfloat16 h0 = __float2bfloat16(f0);
                    __nv_bfloat16 h1 = __float2bfloat16(f1);
                    size_t o = (size_t)rr * HD + col;
                    g_Mh[o] = h0;
                    g_Mh[o + 1] = h1;
                    g_Ml[o] = __float2bfloat16(f0 - __bfloat162float(h0));
                    g_Ml[o + 1] = __float2bfloat16(f1 - __bfloat162float(h1));
                }
            }
        }
    }
}

// ------------------- LayerNorm -------------------
__global__ void ln_kernel(const float* __restrict__ gamma, const float* __restrict__ beta,
                          float* __restrict__ out) {
    const int r = blockIdx.x;
    const int tid = threadIdx.x;      // 256 threads, 8 floats each
    const float* row = g_h + (size_t)r * HD;
    float4 a = *reinterpret_cast<const float4*>(row + tid * 4);
    float4 b = *reinterpret_cast<const float4*>(row + 1024 + tid * 4);
    float s = a.x + a.y + a.z + a.w + b.x + b.y + b.z + b.w;
    float q = a.x * a.x + a.y * a.y + a.z * a.z + a.w * a.w
            + b.x * b.x + b.y * b.y + b.z * b.z + b.w * b.w;
    #pragma unroll
    for (int o = 16; o; o >>= 1) {
        s += __shfl_xor_sync(0xFFFFFFFFu, s, o);
        q += __shfl_xor_sync(0xFFFFFFFFu, q, o);
    }
    __shared__ float ss[8], qq[8];
    __shared__ float mu_s, ri_s;
    if ((tid & 31) == 0) { ss[tid >> 5] = s; qq[tid >> 5] = q; }
    __syncthreads();
    if (tid == 0) {
        float S = 0.f, Q = 0.f;
        #pragma unroll
        for (int i = 0; i < 8; ++i) { S += ss[i]; Q += qq[i]; }
        float mu = S / (float)HD;
        float var = Q / (float)HD - mu * mu;
        mu_s = mu;
        ri_s = rsqrtf(var + LN_EPS);
    }
    __syncthreads();
    const float mu = mu_s, ri = ri_s;
    float4 g1 = *reinterpret_cast<const float4*>(gamma + tid * 4);
    float4 b1 = *reinterpret_cast<const float4*>(beta + tid * 4);
    float4 g2 = *reinterpret_cast<const float4*>(gamma + 1024 + tid * 4);
    float4 b2 = *reinterpret_cast<const float4*>(beta + 1024 + tid * 4);
    float4 o1, o2;
    o1.x = (a.x - mu) * ri * g1.x + b1.x;
    o1.y = (a.y - mu) * ri * g1.y + b1.y;
    o1.z = (a.z - mu) * ri * g1.z + b1.z;
    o1.w = (a.w - mu) * ri * g1.w + b1.w;
    o2.x = (b.x - mu) * ri * g2.x + b2.x;
    o2.y = (b.y - mu) * ri * g2.y + b2.y;
    o2.z = (b.z - mu) * ri * g2.z + b2.z;
    o2.w = (b.w - mu) * ri * g2.w + b2.w;
    float* orow = out + (size_t)r * HD;
    *reinterpret_cast<float4*>(orow + tid * 4) = o1;
    *reinterpret_cast<float4*>(orow + 1024 + tid * 4) = o2;
}

// ------------------- launch -------------------
extern "C" void kernel_launch(void* const* d_in, const int* in_sizes, int n_in,
                              void* d_out, int out_size) {
    const float* x     = (const float*)d_in[0];
    const float* w_qkv = (const float*)d_in[1];
    const float* s_qkv = (const float*)d_in[2];
    const float* w_z   = (const float*)d_in[3];
    const float* s_z   = (const float*)d_in[4];
    const float* w_b   = (const float*)d_in[5];
    const float* s_b   = (const float*)d_in[6];
    const float* w_a   = (const float*)d_in[7];
    const float* s_a   = (const float*)d_in[8];
    const float* d_qkv = (const float*)d_in[9];
    const float* d_z   = (const float*)d_in[10];
    const float* d_b   = (const float*)d_in[11];
    const float* d_a   = (const float*)d_in[12];
    const float* gamma = (const float*)d_in[13];
    const float* beta  = (const float*)d_in[14];
    float* out = (float*)d_out;

    cudaFuncSetAttribute(gemm_kernel, cudaFuncAttributeMaxDynamicSharedMemorySize, SMEM_REQ);

    // prep: split x
    split_x_kernel<<<(NR * HD) / 256, 256>>>(x);

    // prep: concat-split D matrices into A planes   (col bases: 0, 8192, 12288, 13312)
    splitcat_kernel<<<(HD * 8192) / 256, 256>>>(d_qkv, 13, 0);
    splitcat_kernel<<<(HD * 4096) / 256, 256>>>(d_z,   12, 8192);
    splitcat_kernel<<<(HD * 1024) / 256, 256>>>(d_b,   10, 12288);
    splitcat_kernel<<<(HD * 1024) / 256, 256>>>(d_a,   10, 13312);

    // prep: transpose + scale W matrices into B planes
    dim3 tb(32, 8);
    wtrans_kernel<<<dim3(HD / 32, 8192 / 32), tb>>>(w_qkv, s_qkv, 0);
    wtrans_kernel<<<dim3(HD / 32, 4096 / 32), tb>>>(w_z,   s_z,   8192);
    wtrans_kernel<<<dim3(HD / 32, 1024 / 32), tb>>>(w_b,   s_b,   12288);
    wtrans_kernel<<<dim3(HD / 32, 1024 / 32), tb>>>(w_a,   s_a,   13312);

    // GEMM1: M[2048,2048] = A . B^T (K = 14336), split into bf16 planes
    gemm_kernel<<<dim3(HD / 128, HD / 128), 256, SMEM_REQ>>>(0);

    // GEMM2: h[8192,2048] = x . M^T (K = 2048), fp32
    gemm_kernel<<<dim3(HD / 128, NR / 128), 256, SMEM_REQ>>>(1);

    // LayerNorm
    ln_kernel<<<NR, 256>>>(gamma, beta, out);
}

// round 9
// speedup vs baseline: 1.3597x; 1.3597x over previous
#include <cuda_runtime.h>
#include <cuda_fp16.h>
#include <cstdint>
#include <cstddef>

// ------------------- problem constants -------------------
#define HD    2048        // hidden dim H
#define KTOT  14336       // 8192 + 4096 + 1024 + 1024
#define NR    8192        // rows of x / output
#define LN_EPS 1e-5f

// ------------------- GEMM tiling -------------------
#define STAGES      3
#define CHUNK_K     64                        // fp16 elems per chunk (128 B rows)
#define TILE_B      (128 * 128)               // one 128-row x 64-fp16 tile = 16 KB
#define STAGE_B     (3 * TILE_B)              // A, Bh, Bl = 48 KB
#define SMEM_REQ    (STAGES * STAGE_B)        // 144 KB

#define SWZ128(off) ((off) ^ (((off) >> 3) & 0x70))

// ------------------- device scratch (no allocs allowed) -------------------
__device__ __half g_Ah[(size_t)HD * KTOT];   // concat D, hi only     [2048 x 14336]
__device__ __half g_Bh[(size_t)HD * KTOT];   // (W*scale)^T hi plane  [2048 x 14336]
__device__ __half g_Bl[(size_t)HD * KTOT];   // (W*scale)^T lo plane
__device__ __half g_xh[(size_t)NR * HD];     // x hi only             [8192 x 2048]
__device__ __half g_Mh[(size_t)HD * HD];     // M hi plane            [2048 x 2048]
__device__ __half g_Ml[(size_t)HD * HD];     // M lo plane
__device__ float  g_h [(size_t)NR * HD];     // pre-LN activations

// ------------------- PTX helpers -------------------
__device__ __forceinline__ uint32_t smem_u32(const void* p) {
    uint32_t a;
    asm("{ .reg .u64 t; cvta.to.shared.u64 t, %1; cvt.u32.u64 %0, t; }" : "=r"(a) : "l"(p));
    return a;
}

__device__ __forceinline__ void cp_async16(uint32_t saddr, const void* gaddr) {
    asm volatile("cp.async.cg.shared.global [%0], [%1], 16;" :: "r"(saddr), "l"(gaddr));
}

__device__ __forceinline__ void ldsm4(uint32_t* r, uint32_t addr) {
    asm volatile("ldmatrix.sync.aligned.m8n8.x4.shared.b16 {%0,%1,%2,%3}, [%4];"
                 : "=r"(r[0]), "=r"(r[1]), "=r"(r[2]), "=r"(r[3]) : "r"(addr));
}

__device__ __forceinline__ void mma_fp16(float* c, const uint32_t* a, const uint32_t* b) {
    asm volatile(
        "mma.sync.aligned.m16n8k16.row.col.f32.f16.f16.f32 "
        "{%0,%1,%2,%3}, {%4,%5,%6,%7}, {%8,%9}, {%0,%1,%2,%3};"
        : "+f"(c[0]), "+f"(c[1]), "+f"(c[2]), "+f"(c[3])
        : "r"(a[0]), "r"(a[1]), "r"(a[2]), "r"(a[3]), "r"(b[0]), "r"(b[1]));
}

// ------------------- prep kernels -------------------

// x -> fp16 hi plane only (A-side of GEMM2)
__global__ void split_x_kernel(const float* __restrict__ src) {
    size_t i = (size_t)blockIdx.x * blockDim.x + threadIdx.x;
    g_xh[i] = __float2half(src[i]);
}

// D matrix [HD, P] -> concat A plane (hi only) at column offset colbase
__global__ void splitcat_kernel(const float* __restrict__ src, int pshift, int colbase) {
    size_t i = (size_t)blockIdx.x * blockDim.x + threadIdx.x;
    int P = 1 << pshift;
    size_t j = i >> pshift;
    int    p = (int)(i & (size_t)(P - 1));
    g_Ah[j * KTOT + colbase + p] = __float2half(src[i]);
}

// transpose + block-scale W [P, HD] into B hi/lo planes [HD, KTOT] at col offset colbase
__global__ void wtrans_kernel(const float* __restrict__ W, const float* __restrict__ S,
                              int colbase) {
    __shared__ float t[32][33];
    int n0 = blockIdx.x * 32;
    int p0 = blockIdx.y * 32;
    int tx = threadIdx.x, ty = threadIdx.y;       // block (32, 8)
    float sc = S[(p0 >> 7) * (HD >> 7) + (n0 >> 7)];
    #pragma unroll
    for (int r = 0; r < 4; ++r)
        t[ty + r * 8][tx] = W[(size_t)(p0 + ty + r * 8) * HD + n0 + tx];
    __syncthreads();
    #pragma unroll
    for (int r = 0; r < 4; ++r) {
        int n = n0 + ty + r * 8;
        int p = p0 + tx;
        float v = t[tx][ty + r * 8] * sc;
        __half hi = __float2half(v);
        size_t o = (size_t)n * KTOT + colbase + p;
        g_Bh[o] = hi;
        g_Bl[o] = __float2half(v - __half2float(hi));
    }
}

// ------------------- main GEMM (fp16 2-product: Ah*Bh + Ah*Bl) -------------------
// mode 0:  M = A . B^T over K=KTOT, write fp16 hi/lo planes g_Mh/g_Ml
// mode 1:  h = x . M^T over K=HD,   write fp32 g_h
__global__ void __launch_bounds__(256, 1) gemm_kernel(int mode) {
    const __half *A, *Bh, *Bl;
    int K;
    if (mode == 0) { A = g_Ah; Bh = g_Bh; Bl = g_Bl; K = KTOT; }
    else           { A = g_xh; Bh = g_Mh; Bl = g_Ml; K = HD;   }

    extern __shared__ __align__(1024) char smem[];
    const uint32_t sb = smem_u32(smem);

    const int tid = threadIdx.x;
    const int wid = tid >> 5;
    const int lid = tid & 31;
    const int m0 = blockIdx.y * 128;   // output rows  (A rows)
    const int n0 = blockIdx.x * 128;   // output cols  (B rows)
    const int wm = (wid & 1) * 64;     // warp row offset in tile
    const int wn = (wid >> 1) * 32;    // warp col offset in tile

    const int NC = K / CHUNK_K;

    // ---- chunk loader: 12 x cp.async(16B) per thread (3 planes) ----
    auto load_chunk = [&](int c, int s) {
        const int k0 = c * CHUNK_K;
        const uint32_t stage = sb + s * STAGE_B;
        #pragma unroll
        for (int i = 0; i < 4; ++i) {
            int idx = tid + i * 256;           // 0..1023
            int row = idx >> 3;                // 0..127
            int seg = idx & 7;                 // 16B segment
            uint32_t sw = SWZ128((uint32_t)(row * 128 + seg * 16));
            size_t aoff = (size_t)(m0 + row) * K + k0 + seg * 8;
            size_t boff = (size_t)(n0 + row) * K + k0 + seg * 8;
            cp_async16(stage + sw,              A  + aoff);
            cp_async16(stage + TILE_B + sw,     Bh + boff);
            cp_async16(stage + 2 * TILE_B + sw, Bl + boff);
        }
        asm volatile("cp.async.commit_group;" ::: "memory");
    };

    // prologue: stages 0, 1
    load_chunk(0, 0);
    load_chunk(1, 1);

    float acc[4][4][4];
    #pragma unroll
    for (int i = 0; i < 4; ++i)
        #pragma unroll
        for (int j = 0; j < 4; ++j)
            #pragma unroll
            for (int q = 0; q < 4; ++q) acc[i][j][q] = 0.f;

    // ldmatrix address pattern bits (per lane)
    const int lrow = lid & 7;          // row within 8x8 matrix
    const int lmat = lid >> 3;         // which of the 4 matrices

    for (int c = 0; c < NC; ++c) {
        if (c == NC - 1) asm volatile("cp.async.wait_group 0;" ::: "memory");
        else             asm volatile("cp.async.wait_group 1;" ::: "memory");
        __syncthreads();

        const uint32_t stage = sb + (c % STAGES) * STAGE_B;
        const uint32_t tA  = stage;
        const uint32_t tBh = stage + TILE_B;
        const uint32_t tBl = stage + 2 * TILE_B;

        #pragma unroll
        for (int ks = 0; ks < 4; ++ks) {
            const int kb = ks * 32;    // byte offset of this k16 step

            // B fragments: x4 covers 2 n-tiles
            uint32_t bh[4][2], bl[4][2];
            #pragma unroll
            for (int jp = 0; jp < 2; ++jp) {
                int brow = wn + jp * 16 + ((lmat >> 1) ? 8 : 0) + lrow;
                int bcol = kb + ((lmat & 1) ? 16 : 0);
                uint32_t ad = SWZ128((uint32_t)(brow * 128 + bcol));
                uint32_t r[4];
                ldsm4(r, tBh + ad);
                bh[jp * 2 + 0][0] = r[0]; bh[jp * 2 + 0][1] = r[1];
                bh[jp * 2 + 1][0] = r[2]; bh[jp * 2 + 1][1] = r[3];
                ldsm4(r, tBl + ad);
                bl[jp * 2 + 0][0] = r[0]; bl[jp * 2 + 0][1] = r[1];
                bl[jp * 2 + 1][0] = r[2]; bl[jp * 2 + 1][1] = r[3];
            }

            // A fragments (hi plane only)
            uint32_t af[4][4];
            #pragma unroll
            for (int i = 0; i < 4; ++i) {
                int arow = wm + i * 16 + ((lmat & 1) ? 8 : 0) + lrow;
                int acol = kb + ((lmat & 2) ? 16 : 0);
                ldsm4(af[i], tA + SWZ128((uint32_t)(arow * 128 + acol)));
            }

            // 2 products: Ah*Bh + Ah*Bl  (same fp32 accumulator)
            #pragma unroll
            for (int i = 0; i < 4; ++i)
                #pragma unroll
                for (int j = 0; j < 4; ++j) {
                    mma_fp16(acc[i][j], af[i], bh[j]);
                    mma_fp16(acc[i][j], af[i], bl[j]);
                }
        }

        if (c + 2 < NC) load_chunk(c + 2, (c + 2) % STAGES);
    }

    // ---- epilogue: write accumulators ----
    const int g = lid >> 2;            // row group in fragment
    const int t4 = lid & 3;            // col pair
    #pragma unroll
    for (int i = 0; i < 4; ++i) {
        #pragma unroll
        for (int j = 0; j < 4; ++j) {
            int row = m0 + wm + i * 16 + g;
            int col = n0 + wn + j * 8 + 2 * t4;
            if (mode == 1) {
                float2 v0 = make_float2(acc[i][j][0], acc[i][j][1]);
                float2 v1 = make_float2(acc[i][j][2], acc[i][j][3]);
                *reinterpret_cast<float2*>(g_h + (size_t)row * HD + col) = v0;
                *reinterpret_cast<float2*>(g_h + (size_t)(row + 8) * HD + col) = v1;
            } else {
                #pragma unroll
                for (int h = 0; h < 2; ++h) {
                    int rr = row + h * 8;
                    float f0 = acc[i][j][2 * h], f1 = acc[i][j][2 * h + 1];
                    __half h0 = __float2half(f0);
                    __half h1 = __float2half(f1);
                    size_t o = (size_t)rr * HD + col;
                    g_Mh[o] = h0;
                    g_Mh[o + 1] = h1;
                    g_Ml[o] = __float2half(f0 - __half2float(h0));
                    g_Ml[o + 1] = __float2half(f1 - __half2float(h1));
                }
            }
        }
    }
}

// ------------------- LayerNorm -------------------
__global__ void ln_kernel(const float* __restrict__ gamma, const float* __restrict__ beta,
                          float* __restrict__ out) {
    const int r = blockIdx.x;
    const int tid = threadIdx.x;      // 256 threads, 8 floats each
    const float* row = g_h + (size_t)r * HD;
    float4 a = *reinterpret_cast<const float4*>(row + tid * 4);
    float4 b = *reinterpret_cast<const float4*>(row + 1024 + tid * 4);
    float s = a.x + a.y + a.z + a.w + b.x + b.y + b.z + b.w;
    float q = a.x * a.x + a.y * a.y + a.z * a.z + a.w * a.w
            + b.x * b.x + b.y * b.y + b.z * b.z + b.w * b.w;
    #pragma unroll
    for (int o = 16; o; o >>= 1) {
        s += __shfl_xor_sync(0xFFFFFFFFu, s, o);
        q += __shfl_xor_sync(0xFFFFFFFFu, q, o);
    }
    __shared__ float ss[8], qq[8];
    __shared__ float mu_s, ri_s;
    if ((tid & 31) == 0) { ss[tid >> 5] = s; qq[tid >> 5] = q; }
    __syncthreads();
    if (tid == 0) {
        float S = 0.f, Q = 0.f;
        #pragma unroll
        for (int i = 0; i < 8; ++i) { S += ss[i]; Q += qq[i]; }
        float mu = S / (float)HD;
        float var = Q / (float)HD - mu * mu;
        mu_s = mu;
        ri_s = rsqrtf(var + LN_EPS);
    }
    __syncthreads();
    const float mu = mu_s, ri = ri_s;
    float4 g1 = *reinterpret_cast<const float4*>(gamma + tid * 4);
    float4 b1 = *reinterpret_cast<const float4*>(beta + tid * 4);
    float4 g2 = *reinterpret_cast<const float4*>(gamma + 1024 + tid * 4);
    float4 b2 = *reinterpret_cast<const float4*>(beta + 1024 + tid * 4);
    float4 o1, o2;
    o1.x = (a.x - mu) * ri * g1.x + b1.x;
    o1.y = (a.y - mu) * ri * g1.y + b1.y;
    o1.z = (a.z - mu) * ri * g1.z + b1.z;
    o1.w = (a.w - mu) * ri * g1.w + b1.w;
    o2.x = (b.x - mu) * ri * g2.x + b2.x;
    o2.y = (b.y - mu) * ri * g2.y + b2.y;
    o2.z = (b.z - mu) * ri * g2.z + b2.z;
    o2.w = (b.w - mu) * ri * g2.w + b2.w;
    float* orow = out + (size_t)r * HD;
    *reinterpret_cast<float4*>(orow + tid * 4) = o1;
    *reinterpret_cast<float4*>(orow + 1024 + tid * 4) = o2;
}

// ------------------- launch -------------------
extern "C" void kernel_launch(void* const* d_in, const int* in_sizes, int n_in,
                              void* d_out, int out_size) {
    const float* x     = (const float*)d_in[0];
    const float* w_qkv = (const float*)d_in[1];
    const float* s_qkv = (const float*)d_in[2];
    const float* w_z   = (const float*)d_in[3];
    const float* s_z   = (const float*)d_in[4];
    const float* w_b   = (const float*)d_in[5];
    const float* s_b   = (const float*)d_in[6];
    const float* w_a   = (const float*)d_in[7];
    const float* s_a   = (const float*)d_in[8];
    const float* d_qkv = (const float*)d_in[9];
    const float* d_z   = (const float*)d_in[10];
    const float* d_b   = (const float*)d_in[11];
    const float* d_a   = (const float*)d_in[12];
    const float* gamma = (const float*)d_in[13];
    const float* beta  = (const float*)d_in[14];
    float* out = (float*)d_out;

    cudaFuncSetAttribute(gemm_kernel, cudaFuncAttributeMaxDynamicSharedMemorySize, SMEM_REQ);

    // prep: x -> fp16 hi plane
    split_x_kernel<<<(NR * HD) / 256, 256>>>(x);

    // prep: concat D matrices into A plane (col bases: 0, 8192, 12288, 13312)
    splitcat_kernel<<<(HD * 8192) / 256, 256>>>(d_qkv, 13, 0);
    splitcat_kernel<<<(HD * 4096) / 256, 256>>>(d_z,   12, 8192);
    splitcat_kernel<<<(HD * 1024) / 256, 256>>>(d_b,   10, 12288);
    splitcat_kernel<<<(HD * 1024) / 256, 256>>>(d_a,   10, 13312);

    // prep: transpose + scale W matrices into B hi/lo planes
    dim3 tb(32, 8);
    wtrans_kernel<<<dim3(HD / 32, 8192 / 32), tb>>>(w_qkv, s_qkv, 0);
    wtrans_kernel<<<dim3(HD / 32, 4096 / 32), tb>>>(w_z,   s_z,   8192);
    wtrans_kernel<<<dim3(HD / 32, 1024 / 32), tb>>>(w_b,   s_b,   12288);
    wtrans_kernel<<<dim3(HD / 32, 1024 / 32), tb>>>(w_a,   s_a,   13312);

    // GEMM1: M[2048,2048] = A . B^T (K = 14336), split into fp16 planes
    gemm_kernel<<<dim3(HD / 128, HD / 128), 256, SMEM_REQ>>>(0);

    // GEMM2: h[8192,2048] = x . M^T (K = 2048), fp32
    gemm_kernel<<<dim3(HD / 128, NR / 128), 256, SMEM_REQ>>>(1);

    // LayerNorm
    ln_kernel<<<NR, 256>>>(gamma, beta, out);
}

// round 11
// speedup vs baseline: 2.0317x; 1.4942x over previous
#include <cuda_runtime.h>
#include <cuda_fp16.h>
#include <cstdint>
#include <cstddef>

// ------------------- problem constants -------------------
#define HD    2048        // hidden dim H
#define KTOT  14336       // 8192 + 4096 + 1024 + 1024
#define NR    8192        // rows of x / output
#define LN_EPS 1e-5f

// ------------------- GEMM tiling -------------------
#define STAGES      3
#define CHUNK_K     64                        // fp16 elems per chunk (128 B rows)
#define TILE_B      (128 * 128)               // one 128-row x 64-fp16 tile = 16 KB
#define STAGE_B     (2 * TILE_B)              // A, B = 32 KB
#define SMEM_REQ    (STAGES * STAGE_B)        // 96 KB

#define SWZ128(off) ((off) ^ (((off) >> 3) & 0x70))

// ------------------- device scratch (no allocs allowed) -------------------
__device__ __half g_A [(size_t)HD * KTOT];   // concat D (fp16)       [2048 x 14336]
__device__ __half g_B [(size_t)HD * KTOT];   // (W*scale)^T (fp16)    [2048 x 14336]
__device__ __half g_x [(size_t)NR * HD];     // x (fp16)              [8192 x 2048]
__device__ __half g_M [(size_t)HD * HD];     // M (fp16)              [2048 x 2048]
__device__ float  g_h [(size_t)NR * HD];     // pre-LN activations

// ------------------- PTX helpers -------------------
__device__ __forceinline__ uint32_t smem_u32(const void* p) {
    uint32_t a;
    asm("{ .reg .u64 t; cvta.to.shared.u64 t, %1; cvt.u32.u64 %0, t; }" : "=r"(a) : "l"(p));
    return a;
}

__device__ __forceinline__ void cp_async16(uint32_t saddr, const void* gaddr) {
    asm volatile("cp.async.cg.shared.global [%0], [%1], 16;" :: "r"(saddr), "l"(gaddr));
}

__device__ __forceinline__ void ldsm4(uint32_t* r, uint32_t addr) {
    asm volatile("ldmatrix.sync.aligned.m8n8.x4.shared.b16 {%0,%1,%2,%3}, [%4];"
                 : "=r"(r[0]), "=r"(r[1]), "=r"(r[2]), "=r"(r[3]) : "r"(addr));
}

__device__ __forceinline__ void mma_fp16(float* c, const uint32_t* a, const uint32_t* b) {
    asm volatile(
        "mma.sync.aligned.m16n8k16.row.col.f32.f16.f16.f32 "
        "{%0,%1,%2,%3}, {%4,%5,%6,%7}, {%8,%9}, {%0,%1,%2,%3};"
        : "+f"(c[0]), "+f"(c[1]), "+f"(c[2]), "+f"(c[3])
        : "r"(a[0]), "r"(a[1]), "r"(a[2]), "r"(a[3]), "r"(b[0]), "r"(b[1]));
}

// ------------------- prep kernels -------------------

// x -> fp16
__global__ void split_x_kernel(const float* __restrict__ src) {
    size_t i = (size_t)blockIdx.x * blockDim.x + threadIdx.x;
    g_x[i] = __float2half(src[i]);
}

// D matrix [HD, P] -> concat A plane at column offset colbase
__global__ void splitcat_kernel(const float* __restrict__ src, int pshift, int colbase) {
    size_t i = (size_t)blockIdx.x * blockDim.x + threadIdx.x;
    int P = 1 << pshift;
    size_t j = i >> pshift;
    int    p = (int)(i & (size_t)(P - 1));
    g_A[j * KTOT + colbase + p] = __float2half(src[i]);
}

// transpose + block-scale ALL W matrices into B [HD, KTOT] (one launch)
__global__ void wtrans_all_kernel(const float* __restrict__ w_qkv, const float* __restrict__ s_qkv,
                                  const float* __restrict__ w_z,   const float* __restrict__ s_z,
                                  const float* __restrict__ w_b,   const float* __restrict__ s_b,
                                  const float* __restrict__ w_a,   const float* __restrict__ s_a) {
    __shared__ float t[32][33];
    int n0 = blockIdx.x * 32;          // HD index
    int gp0 = blockIdx.y * 32;         // global concat-K index (0..14336)

    const float* W; const float* S; int lp0;
    if      (gp0 < 8192)  { W = w_qkv; S = s_qkv; lp0 = gp0;         }
    else if (gp0 < 12288) { W = w_z;   S = s_z;   lp0 = gp0 - 8192;  }
    else if (gp0 < 13312) { W = w_b;   S = s_b;   lp0 = gp0 - 12288; }
    else                  { W = w_a;   S = s_a;   lp0 = gp0 - 13312; }

    int tx = threadIdx.x, ty = threadIdx.y;       // block (32, 8)
    float sc = S[(lp0 >> 7) * (HD >> 7) + (n0 >> 7)];
    #pragma unroll
    for (int r = 0; r < 4; ++r)
        t[ty + r * 8][tx] = W[(size_t)(lp0 + ty + r * 8) * HD + n0 + tx];
    __syncthreads();
    #pragma unroll
    for (int r = 0; r < 4; ++r) {
        int n = n0 + ty + r * 8;
        int p = gp0 + tx;
        float v = t[tx][ty + r * 8] * sc;
        g_B[(size_t)n * KTOT + p] = __float2half(v);
    }
}

// ------------------- main GEMM (single fp16 product) -------------------
// mode 0:  M = A . B^T over K=KTOT, write fp16 g_M
// mode 1:  h = x . M^T over K=HD,   write fp32 g_h
__global__ void __launch_bounds__(256, 1) gemm_kernel(int mode) {
    const __half *A, *B;
    int K;
    if (mode == 0) { A = g_A; B = g_B; K = KTOT; }
    else           { A = g_x; B = g_M; K = HD;   }

    extern __shared__ __align__(1024) char smem[];
    const uint32_t sb = smem_u32(smem);

    const int tid = threadIdx.x;
    const int wid = tid >> 5;
    const int lid = tid & 31;
    const int m0 = blockIdx.y * 128;   // output rows  (A rows)
    const int n0 = blockIdx.x * 128;   // output cols  (B rows)
    const int wm = (wid & 1) * 64;     // warp row offset in tile
    const int wn = (wid >> 1) * 32;    // warp col offset in tile

    const int NC = K / CHUNK_K;

    // ---- chunk loader: 8 x cp.async(16B) per thread (2 planes) ----
    auto load_chunk = [&](int c, int s) {
        const int k0 = c * CHUNK_K;
        const uint32_t stage = sb + s * STAGE_B;
        #pragma unroll
        for (int i = 0; i < 4; ++i) {
            int idx = tid + i * 256;           // 0..1023
            int row = idx >> 3;                // 0..127
            int seg = idx & 7;                 // 16B segment
            uint32_t sw = SWZ128((uint32_t)(row * 128 + seg * 16));
            size_t aoff = (size_t)(m0 + row) * K + k0 + seg * 8;
            size_t boff = (size_t)(n0 + row) * K + k0 + seg * 8;
            cp_async16(stage + sw,          A + aoff);
            cp_async16(stage + TILE_B + sw, B + boff);
        }
        asm volatile("cp.async.commit_group;" ::: "memory");
    };

    // prologue: stages 0, 1
    load_chunk(0, 0);
    load_chunk(1, 1);

    float acc[4][4][4];
    #pragma unroll
    for (int i = 0; i < 4; ++i)
        #pragma unroll
        for (int j = 0; j < 4; ++j)
            #pragma unroll
            for (int q = 0; q < 4; ++q) acc[i][j][q] = 0.f;

    // ldmatrix address pattern bits (per lane)
    const int lrow = lid & 7;          // row within 8x8 matrix
    const int lmat = lid >> 3;         // which of the 4 matrices

    for (int c = 0; c < NC; ++c) {
        if (c == NC - 1) asm volatile("cp.async.wait_group 0;" ::: "memory");
        else             asm volatile("cp.async.wait_group 1;" ::: "memory");
        __syncthreads();

        const uint32_t stage = sb + (c % STAGES) * STAGE_B;
        const uint32_t tA = stage;
        const uint32_t tB = stage + TILE_B;

        #pragma unroll
        for (int ks = 0; ks < 4; ++ks) {
            const int kb = ks * 32;    // byte offset of this k16 step

            // B fragments: x4 covers 2 n-tiles
            uint32_t bf[4][2];
            #pragma unroll
            for (int jp = 0; jp < 2; ++jp) {
                int brow = wn + jp * 16 + ((lmat >> 1) ? 8 : 0) + lrow;
                int bcol = kb + ((lmat & 1) ? 16 : 0);
                uint32_t r[4];
                ldsm4(r, tB + SWZ128((uint32_t)(brow * 128 + bcol)));
                bf[jp * 2 + 0][0] = r[0]; bf[jp * 2 + 0][1] = r[1];
                bf[jp * 2 + 1][0] = r[2]; bf[jp * 2 + 1][1] = r[3];
            }

            // A fragments
            uint32_t af[4][4];
            #pragma unroll
            for (int i = 0; i < 4; ++i) {
                int arow = wm + i * 16 + ((lmat & 1) ? 8 : 0) + lrow;
                int acol = kb + ((lmat & 2) ? 16 : 0);
                ldsm4(af[i], tA + SWZ128((uint32_t)(arow * 128 + acol)));
            }

            #pragma unroll
            for (int i = 0; i < 4; ++i)
                #pragma unroll
                for (int j = 0; j < 4; ++j)
                    mma_fp16(acc[i][j], af[i], bf[j]);
        }

        if (c + 2 < NC) load_chunk(c + 2, (c + 2) % STAGES);
    }

    // ---- epilogue: write accumulators ----
    const int g = lid >> 2;            // row group in fragment
    const int t4 = lid & 3;            // col pair
    #pragma unroll
    for (int i = 0; i < 4; ++i) {
        #pragma unroll
        for (int j = 0; j < 4; ++j) {
            int row = m0 + wm + i * 16 + g;
            int col = n0 + wn + j * 8 + 2 * t4;
            if (mode == 1) {
                float2 v0 = make_float2(acc[i][j][0], acc[i][j][1]);
                float2 v1 = make_float2(acc[i][j][2], acc[i][j][3]);
                *reinterpret_cast<float2*>(g_h + (size_t)row * HD + col) = v0;
                *reinterpret_cast<float2*>(g_h + (size_t)(row + 8) * HD + col) = v1;
            } else {
                __half2 v0 = __halves2half2(__float2half(acc[i][j][0]),
                                            __float2half(acc[i][j][1]));
                __half2 v1 = __halves2half2(__float2half(acc[i][j][2]),
                                            __float2half(acc[i][j][3]));
                *reinterpret_cast<__half2*>(g_M + (size_t)row * HD + col) = v0;
                *reinterpret_cast<__half2*>(g_M + (size_t)(row + 8) * HD + col) = v1;
            }
        }
    }
}

// ------------------- LayerNorm -------------------
__global__ void ln_kernel(const float* __restrict__ gamma, const float* __restrict__ beta,
                          float* __restrict__ out) {
    const int r = blockIdx.x;
    const int tid = threadIdx.x;      // 256 threads, 8 floats each
    const float* row = g_h + (size_t)r * HD;
    float4 a = *reinterpret_cast<const float4*>(row + tid * 4);
    float4 b = *reinterpret_cast<const float4*>(row + 1024 + tid * 4);
    float s = a.x + a.y + a.z + a.w + b.x + b.y + b.z + b.w;
    float q = a.x * a.x + a.y * a.y + a.z * a.z + a.w * a.w
            + b.x * b.x + b.y * b.y + b.z * b.z + b.w * b.w;
    #pragma unroll
    for (int o = 16; o; o >>= 1) {
        s += __shfl_xor_sync(0xFFFFFFFFu, s, o);
        q += __shfl_xor_sync(0xFFFFFFFFu, q, o);
    }
    __shared__ float ss[8], qq[8];
    __shared__ float mu_s, ri_s;
    if ((tid & 31) == 0) { ss[tid >> 5] = s; qq[tid >> 5] = q; }
    __syncthreads();
    if (tid == 0) {
        float S = 0.f, Q = 0.f;
        #pragma unroll
        for (int i = 0; i < 8; ++i) { S += ss[i]; Q += qq[i]; }
        float mu = S / (float)HD;
        float var = Q / (float)HD - mu * mu;
        mu_s = mu;
        ri_s = rsqrtf(var + LN_EPS);
    }
    __syncthreads();
    const float mu = mu_s, ri = ri_s;
    float4 g1 = *reinterpret_cast<const float4*>(gamma + tid * 4);
    float4 b1 = *reinterpret_cast<const float4*>(beta + tid * 4);
    float4 g2 = *reinterpret_cast<const float4*>(gamma + 1024 + tid * 4);
    float4 b2 = *reinterpret_cast<const float4*>(beta + 1024 + tid * 4);
    float4 o1, o2;
    o1.x = (a.x - mu) * ri * g1.x + b1.x;
    o1.y = (a.y - mu) * ri * g1.y + b1.y;
    o1.z = (a.z - mu) * ri * g1.z + b1.z;
    o1.w = (a.w - mu) * ri * g1.w + b1.w;
    o2.x = (b.x - mu) * ri * g2.x + b2.x;
    o2.y = (b.y - mu) * ri * g2.y + b2.y;
    o2.z = (b.z - mu) * ri * g2.z + b2.z;
    o2.w = (b.w - mu) * ri * g2.w + b2.w;
    float* orow = out + (size_t)r * HD;
    *reinterpret_cast<float4*>(orow + tid * 4) = o1;
    *reinterpret_cast<float4*>(orow + 1024 + tid * 4) = o2;
}

// ------------------- launch -------------------
extern "C" void kernel_launch(void* const* d_in, const int* in_sizes, int n_in,
                              void* d_out, int out_size) {
    const float* x     = (const float*)d_in[0];
    const float* w_qkv = (const float*)d_in[1];
    const float* s_qkv = (const float*)d_in[2];
    const float* w_z   = (const float*)d_in[3];
    const float* s_z   = (const float*)d_in[4];
    const float* w_b   = (const float*)d_in[5];
    const float* s_b   = (const float*)d_in[6];
    const float* w_a   = (const float*)d_in[7];
    const float* s_a   = (const float*)d_in[8];
    const float* d_qkv = (const float*)d_in[9];
    const float* d_z   = (const float*)d_in[10];
    const float* d_b   = (const float*)d_in[11];
    const float* d_a   = (const float*)d_in[12];
    const float* gamma = (const float*)d_in[13];
    const float* beta  = (const float*)d_in[14];
    float* out = (float*)d_out;

    cudaFuncSetAttribute(gemm_kernel, cudaFuncAttributeMaxDynamicSharedMemorySize, SMEM_REQ);

    // launches 1-4: concat D matrices into A (col bases: 0, 8192, 12288, 13312)
    splitcat_kernel<<<(HD * 8192) / 256, 256>>>(d_qkv, 13, 0);
    splitcat_kernel<<<(HD * 4096) / 256, 256>>>(d_z,   12, 8192);
    splitcat_kernel<<<(HD * 1024) / 256, 256>>>(d_b,   10, 12288);
    splitcat_kernel<<<(HD * 1024) / 256, 256>>>(d_a,   10, 13312);

    // launch 5: transpose + scale all W matrices into B (single launch)
    wtrans_all_kernel<<<dim3(HD / 32, KTOT / 32), dim3(32, 8)>>>(
        w_qkv, s_qkv, w_z, s_z, w_b, s_b, w_a, s_a);

    // launch 6 (ncu -s 5 captures this): GEMM1  M = A . B^T (K = 14336)
    gemm_kernel<<<dim3(HD / 128, HD / 128), 256, SMEM_REQ>>>(0);

    // launch 7: x -> fp16 (only needed by GEMM2)
    split_x_kernel<<<(NR * HD) / 256, 256>>>(x);

    // launch 8: GEMM2  h = x . M^T (K = 2048)
    gemm_kernel<<<dim3(HD / 128, NR / 128), 256, SMEM_REQ>>>(1);

    // launch 9: LayerNorm
    ln_kernel<<<NR, 256>>>(gamma, beta, out);
}

// round 12
// speedup vs baseline: 2.2178x; 1.0916x over previous
#include <cuda_runtime.h>
#include <cuda_fp16.h>
#include <cstdint>
#include <cstddef>

// ------------------- problem constants -------------------
#define HD    2048        // hidden dim H
#define KTOT  14336       // 8192 + 4096 + 1024 + 1024
#define NR    8192        // rows of x / output
#define LN_EPS 1e-5f

// ------------------- GEMM tiling -------------------
// CTA tile 128 (M) x 256 (N), warp tile 64x64, 8 warps, K-chunk 64
#define STAGES      3
#define CHUNK_K     64                        // fp16 elems per chunk (128 B rows)
#define TILE_A_B    (128 * 128)               // A tile: 128 rows x 128 B = 16 KB
#define TILE_B_B    (256 * 128)               // B tile: 256 rows x 128 B = 32 KB
#define STAGE_B     (TILE_A_B + TILE_B_B)     // 48 KB
#define SMEM_REQ    (STAGES * STAGE_B)        // 144 KB

#define SWZ128(off) ((off) ^ (((off) >> 3) & 0x70))

// ------------------- device scratch (no allocs allowed) -------------------
__device__ __half g_A [(size_t)HD * KTOT];   // concat D (fp16)       [2048 x 14336]
__device__ __half g_B [(size_t)HD * KTOT];   // (W*scale)^T (fp16)    [2048 x 14336]
__device__ __half g_x [(size_t)NR * HD];     // x (fp16)              [8192 x 2048]
__device__ __half g_M [(size_t)HD * HD];     // M (fp16)              [2048 x 2048]
__device__ float  g_h [(size_t)NR * HD];     // pre-LN activations

// ------------------- PTX helpers -------------------
__device__ __forceinline__ uint32_t smem_u32(const void* p) {
    uint32_t a;
    asm("{ .reg .u64 t; cvta.to.shared.u64 t, %1; cvt.u32.u64 %0, t; }" : "=r"(a) : "l"(p));
    return a;
}

__device__ __forceinline__ void cp_async16(uint32_t saddr, const void* gaddr) {
    asm volatile("cp.async.cg.shared.global [%0], [%1], 16;" :: "r"(saddr), "l"(gaddr));
}

__device__ __forceinline__ void ldsm4(uint32_t* r, uint32_t addr) {
    asm volatile("ldmatrix.sync.aligned.m8n8.x4.shared.b16 {%0,%1,%2,%3}, [%4];"
                 : "=r"(r[0]), "=r"(r[1]), "=r"(r[2]), "=r"(r[3]) : "r"(addr));
}

__device__ __forceinline__ void mma_fp16(float* c, const uint32_t* a, const uint32_t* b) {
    asm volatile(
        "mma.sync.aligned.m16n8k16.row.col.f32.f16.f16.f32 "
        "{%0,%1,%2,%3}, {%4,%5,%6,%7}, {%8,%9}, {%0,%1,%2,%3};"
        : "+f"(c[0]), "+f"(c[1]), "+f"(c[2]), "+f"(c[3])
        : "r"(a[0]), "r"(a[1]), "r"(a[2]), "r"(a[3]), "r"(b[0]), "r"(b[1]));
}

// ------------------- prep kernels -------------------

// x -> fp16
__global__ void split_x_kernel(const float* __restrict__ src) {
    size_t i = (size_t)blockIdx.x * blockDim.x + threadIdx.x;
    g_x[i] = __float2half(src[i]);
}

// D matrix [HD, P] -> concat A plane at column offset colbase
__global__ void splitcat_kernel(const float* __restrict__ src, int pshift, int colbase) {
    size_t i = (size_t)blockIdx.x * blockDim.x + threadIdx.x;
    int P = 1 << pshift;
    size_t j = i >> pshift;
    int    p = (int)(i & (size_t)(P - 1));
    g_A[j * KTOT + colbase + p] = __float2half(src[i]);
}

// transpose + block-scale ALL W matrices into B [HD, KTOT] (one launch)
__global__ void wtrans_all_kernel(const float* __restrict__ w_qkv, const float* __restrict__ s_qkv,
                                  const float* __restrict__ w_z,   const float* __restrict__ s_z,
                                  const float* __restrict__ w_b,   const float* __restrict__ s_b,
                                  const float* __restrict__ w_a,   const float* __restrict__ s_a) {
    __shared__ float t[32][33];
    int n0 = blockIdx.x * 32;          // HD index
    int gp0 = blockIdx.y * 32;         // global concat-K index (0..14336)

    const float* W; const float* S; int lp0;
    if      (gp0 < 8192)  { W = w_qkv; S = s_qkv; lp0 = gp0;         }
    else if (gp0 < 12288) { W = w_z;   S = s_z;   lp0 = gp0 - 8192;  }
    else if (gp0 < 13312) { W = w_b;   S = s_b;   lp0 = gp0 - 12288; }
    else                  { W = w_a;   S = s_a;   lp0 = gp0 - 13312; }

    int tx = threadIdx.x, ty = threadIdx.y;       // block (32, 8)
    float sc = S[(lp0 >> 7) * (HD >> 7) + (n0 >> 7)];
    #pragma unroll
    for (int r = 0; r < 4; ++r)
        t[ty + r * 8][tx] = W[(size_t)(lp0 + ty + r * 8) * HD + n0 + tx];
    __syncthreads();
    #pragma unroll
    for (int r = 0; r < 4; ++r) {
        int n = n0 + ty + r * 8;
        int p = gp0 + tx;
        float v = t[tx][ty + r * 8] * sc;
        g_B[(size_t)n * KTOT + p] = __float2half(v);
    }
}

// ------------------- main GEMM (single fp16 product, 128x256 CTA tile) -------------------
// mode 0:  M = A . B^T over K=KTOT, write fp16 g_M
// mode 1:  h = x . M^T over K=HD,   write fp32 g_h
__global__ void __launch_bounds__(256, 1) gemm_kernel(int mode) {
    const __half *A, *B;
    int K;
    if (mode == 0) { A = g_A; B = g_B; K = KTOT; }
    else           { A = g_x; B = g_M; K = HD;   }

    extern __shared__ __align__(1024) char smem[];
    const uint32_t sb = smem_u32(smem);

    const int tid = threadIdx.x;
    const int wid = tid >> 5;
    const int lid = tid & 31;
    const int m0 = blockIdx.y * 128;   // output rows  (A rows)
    const int n0 = blockIdx.x * 256;   // output cols  (B rows)
    const int wm = (wid & 1) * 64;     // warp row offset in tile
    const int wn = (wid >> 1) * 64;    // warp col offset in tile

    const int NC = K / CHUNK_K;

    // ---- chunk loader: 12 x cp.async(16B) per thread ----
    auto load_chunk = [&](int c, int s) {
        const int k0 = c * CHUNK_K;
        const uint32_t stage = sb + s * STAGE_B;
        // A tile: 128 rows x 128 B
        #pragma unroll
        for (int i = 0; i < 4; ++i) {
            int idx = tid + i * 256;           // 0..1023
            int row = idx >> 3;                // 0..127
            int seg = idx & 7;
            uint32_t sw = SWZ128((uint32_t)(row * 128 + seg * 16));
            cp_async16(stage + sw, A + (size_t)(m0 + row) * K + k0 + seg * 8);
        }
        // B tile: 256 rows x 128 B
        #pragma unroll
        for (int i = 0; i < 8; ++i) {
            int idx = tid + i * 256;           // 0..2047
            int row = idx >> 3;                // 0..255
            int seg = idx & 7;
            uint32_t sw = SWZ128((uint32_t)(row * 128 + seg * 16));
            cp_async16(stage + TILE_A_B + sw, B + (size_t)(n0 + row) * K + k0 + seg * 8);
        }
        asm volatile("cp.async.commit_group;" ::: "memory");
    };

    // prologue: stages 0, 1
    load_chunk(0, 0);
    load_chunk(1, 1);

    float acc[4][8][4];
    #pragma unroll
    for (int i = 0; i < 4; ++i)
        #pragma unroll
        for (int j = 0; j < 8; ++j)
            #pragma unroll
            for (int q = 0; q < 4; ++q) acc[i][j][q] = 0.f;

    // ldmatrix address pattern bits (per lane)
    const int lrow = lid & 7;          // row within 8x8 matrix
    const int lmat = lid >> 3;         // which of the 4 matrices

    for (int c = 0; c < NC; ++c) {
        if (c == NC - 1) asm volatile("cp.async.wait_group 0;" ::: "memory");
        else             asm volatile("cp.async.wait_group 1;" ::: "memory");
        __syncthreads();

        const uint32_t stage = sb + (c % STAGES) * STAGE_B;
        const uint32_t tA = stage;
        const uint32_t tB = stage + TILE_A_B;

        #pragma unroll
        for (int ks = 0; ks < 4; ++ks) {
            const int kb = ks * 32;    // byte offset of this k16 step

            // B fragments: 4 x ldsm.x4 covers 8 n-tiles (64 cols)
            uint32_t bf[8][2];
            #pragma unroll
            for (int jp = 0; jp < 4; ++jp) {
                int brow = wn + jp * 16 + ((lmat >> 1) ? 8 : 0) + lrow;
                int bcol = kb + ((lmat & 1) ? 16 : 0);
                uint32_t r[4];
                ldsm4(r, tB + SWZ128((uint32_t)(brow * 128 + bcol)));
                bf[jp * 2 + 0][0] = r[0]; bf[jp * 2 + 0][1] = r[1];
                bf[jp * 2 + 1][0] = r[2]; bf[jp * 2 + 1][1] = r[3];
            }

            // A fragments: 4 x ldsm.x4 covers 64 rows
            uint32_t af[4][4];
            #pragma unroll
            for (int i = 0; i < 4; ++i) {
                int arow = wm + i * 16 + ((lmat & 1) ? 8 : 0) + lrow;
                int acol = kb + ((lmat & 2) ? 16 : 0);
                ldsm4(af[i], tA + SWZ128((uint32_t)(arow * 128 + acol)));
            }

            #pragma unroll
            for (int i = 0; i < 4; ++i)
                #pragma unroll
                for (int j = 0; j < 8; ++j)
                    mma_fp16(acc[i][j], af[i], bf[j]);
        }

        if (c + 2 < NC) load_chunk(c + 2, (c + 2) % STAGES);
    }

    // ---- epilogue: write accumulators ----
    const int g = lid >> 2;            // row group in fragment
    const int t4 = lid & 3;            // col pair
    #pragma unroll
    for (int i = 0; i < 4; ++i) {
        #pragma unroll
        for (int j = 0; j < 8; ++j) {
            int row = m0 + wm + i * 16 + g;
            int col = n0 + wn + j * 8 + 2 * t4;
            if (mode == 1) {
                float2 v0 = make_float2(acc[i][j][0], acc[i][j][1]);
                float2 v1 = make_float2(acc[i][j][2], acc[i][j][3]);
                *reinterpret_cast<float2*>(g_h + (size_t)row * HD + col) = v0;
                *reinterpret_cast<float2*>(g_h + (size_t)(row + 8) * HD + col) = v1;
            } else {
                __half2 v0 = __halves2half2(__float2half(acc[i][j][0]),
                                            __float2half(acc[i][j][1]));
                __half2 v1 = __halves2half2(__float2half(acc[i][j][2]),
                                            __float2half(acc[i][j][3]));
                *reinterpret_cast<__half2*>(g_M + (size_t)row * HD + col) = v0;
                *reinterpret_cast<__half2*>(g_M + (size_t)(row + 8) * HD + col) = v1;
            }
        }
    }
}

// ------------------- LayerNorm -------------------
__global__ void ln_kernel(const float* __restrict__ gamma, const float* __restrict__ beta,
                          float* __restrict__ out) {
    const int r = blockIdx.x;
    const int tid = threadIdx.x;      // 256 threads, 8 floats each
    const float* row = g_h + (size_t)r * HD;
    float4 a = *reinterpret_cast<const float4*>(row + tid * 4);
    float4 b = *reinterpret_cast<const float4*>(row + 1024 + tid * 4);
    float s = a.x + a.y + a.z + a.w + b.x + b.y + b.z + b.w;
    float q = a.x * a.x + a.y * a.y + a.z * a.z + a.w * a.w
            + b.x * b.x + b.y * b.y + b.z * b.z + b.w * b.w;
    #pragma unroll
    for (int o = 16; o; o >>= 1) {
        s += __shfl_xor_sync(0xFFFFFFFFu, s, o);
        q += __shfl_xor_sync(0xFFFFFFFFu, q, o);
    }
    __shared__ float ss[8], qq[8];
    __shared__ float mu_s, ri_s;
    if ((tid & 31) == 0) { ss[tid >> 5] = s; qq[tid >> 5] = q; }
    __syncthreads();
    if (tid == 0) {
        float S = 0.f, Q = 0.f;
        #pragma unroll
        for (int i = 0; i < 8; ++i) { S += ss[i]; Q += qq[i]; }
        float mu = S / (float)HD;
        float var = Q / (float)HD - mu * mu;
        mu_s = mu;
        ri_s = rsqrtf(var + LN_EPS);
    }
    __syncthreads();
    const float mu = mu_s, ri = ri_s;
    float4 g1 = *reinterpret_cast<const float4*>(gamma + tid * 4);
    float4 b1 = *reinterpret_cast<const float4*>(beta + tid * 4);
    float4 g2 = *reinterpret_cast<const float4*>(gamma + 1024 + tid * 4);
    float4 b2 = *reinterpret_cast<const float4*>(beta + 1024 + tid * 4);
    float4 o1, o2;
    o1.x = (a.x - mu) * ri * g1.x + b1.x;
    o1.y = (a.y - mu) * ri * g1.y + b1.y;
    o1.z = (a.z - mu) * ri * g1.z + b1.z;
    o1.w = (a.w - mu) * ri * g1.w + b1.w;
    o2.x = (b.x - mu) * ri * g2.x + b2.x;
    o2.y = (b.y - mu) * ri * g2.y + b2.y;
    o2.z = (b.z - mu) * ri * g2.z + b2.z;
    o2.w = (b.w - mu) * ri * g2.w + b2.w;
    float* orow = out + (size_t)r * HD;
    *reinterpret_cast<float4*>(orow + tid * 4) = o1;
    *reinterpret_cast<float4*>(orow + 1024 + tid * 4) = o2;
}

// ------------------- launch -------------------
extern "C" void kernel_launch(void* const* d_in, const int* in_sizes, int n_in,
                              void* d_out, int out_size) {
    const float* x     = (const float*)d_in[0];
    const float* w_qkv = (const float*)d_in[1];
    const float* s_qkv = (const float*)d_in[2];
    const float* w_z   = (const float*)d_in[3];
    const float* s_z   = (const float*)d_in[4];
    const float* w_b   = (const float*)d_in[5];
    const float* s_b   = (const float*)d_in[6];
    const float* w_a   = (const float*)d_in[7];
    const float* s_a   = (const float*)d_in[8];
    const float* d_qkv = (const float*)d_in[9];
    const float* d_z   = (const float*)d_in[10];
    const float* d_b   = (const float*)d_in[11];
    const float* d_a   = (const float*)d_in[12];
    const float* gamma = (const float*)d_in[13];
    const float* beta  = (const float*)d_in[14];
    float* out = (float*)d_out;

    cudaFuncSetAttribute(gemm_kernel, cudaFuncAttributeMaxDynamicSharedMemorySize, SMEM_REQ);

    // launches 1-4: concat D matrices into A (col bases: 0, 8192, 12288, 13312)
    splitcat_kernel<<<(HD * 8192) / 256, 256>>>(d_qkv, 13, 0);
    splitcat_kernel<<<(HD * 4096) / 256, 256>>>(d_z,   12, 8192);
    splitcat_kernel<<<(HD * 1024) / 256, 256>>>(d_b,   10, 12288);
    splitcat_kernel<<<(HD * 1024) / 256, 256>>>(d_a,   10, 13312);

    // launch 5: transpose + scale all W matrices into B (single launch)
    wtrans_all_kernel<<<dim3(HD / 32, KTOT / 32), dim3(32, 8)>>>(
        w_qkv, s_qkv, w_z, s_z, w_b, s_b, w_a, s_a);

    // launch 6: GEMM1  M = A . B^T (K = 14336), 128 CTAs = one wave
    gemm_kernel<<<dim3(HD / 256, HD / 128), 256, SMEM_REQ>>>(0);

    // launch 7: x -> fp16 (only needed by GEMM2)
    split_x_kernel<<<(NR * HD) / 256, 256>>>(x);

    // launch 8: GEMM2  h = x . M^T (K = 2048)
    gemm_kernel<<<dim3(HD / 256, NR / 128), 256, SMEM_REQ>>>(1);

    // launch 9: LayerNorm
    ln_kernel<<<NR, 256>>>(gamma, beta, out);
}

// round 14
// speedup vs baseline: 2.4068x; 1.0852x over previous
#include <cuda_runtime.h>
#include <cuda_fp16.h>
#include <cstdint>
#include <cstddef>

// ------------------- problem constants -------------------
#define HD    2048        // hidden dim H
#define KTOT  14336       // 8192 + 4096 + 1024 + 1024
#define NR    8192        // rows of x / output
#define LN_EPS 1e-5f

// ------------------- GEMM tiling -------------------
// CTA tile 128 (M) x 256 (N), warp tile 64x64, 8 warps, K-chunk 64
#define STAGES      3
#define CHUNK_K     64                        // fp16 elems per chunk (128 B rows)
#define TILE_A_B    (128 * 128)               // A tile: 128 rows x 128 B = 16 KB
#define TILE_B_B    (256 * 128)               // B tile: 256 rows x 128 B = 32 KB
#define STAGE_B     (TILE_A_B + TILE_B_B)     // 48 KB
#define SMEM_REQ    (STAGES * STAGE_B)        // 144 KB

#define SWZ128(off) ((off) ^ (((off) >> 3) & 0x70))

// ------------------- device scratch (no allocs allowed) -------------------
__device__ __half g_A [(size_t)HD * KTOT];   // concat D (fp16)       [2048 x 14336]
__device__ __half g_B [(size_t)HD * KTOT];   // (W*scale)^T (fp16)    [2048 x 14336]
__device__ __half g_x [(size_t)NR * HD];     // x (fp16)              [8192 x 2048]
__device__ __half g_M [(size_t)HD * HD];     // M (fp16)              [2048 x 2048]
__device__ float  g_h [(size_t)NR * HD];     // pre-LN activations

// ------------------- PTX helpers -------------------
__device__ __forceinline__ uint32_t smem_u32(const void* p) {
    uint32_t a;
    asm("{ .reg .u64 t; cvta.to.shared.u64 t, %1; cvt.u32.u64 %0, t; }" : "=r"(a) : "l"(p));
    return a;
}

__device__ __forceinline__ void cp_async16(uint32_t saddr, const void* gaddr) {
    asm volatile("cp.async.cg.shared.global [%0], [%1], 16;" :: "r"(saddr), "l"(gaddr));
}

__device__ __forceinline__ void ldsm4(uint32_t* r, uint32_t addr) {
    asm volatile("ldmatrix.sync.aligned.m8n8.x4.shared.b16 {%0,%1,%2,%3}, [%4];"
                 : "=r"(r[0]), "=r"(r[1]), "=r"(r[2]), "=r"(r[3]) : "r"(addr));
}

__device__ __forceinline__ void mma_fp16(float* c, const uint32_t* a, const uint32_t* b) {
    asm volatile(
        "mma.sync.aligned.m16n8k16.row.col.f32.f16.f16.f32 "
        "{%0,%1,%2,%3}, {%4,%5,%6,%7}, {%8,%9}, {%0,%1,%2,%3};"
        : "+f"(c[0]), "+f"(c[1]), "+f"(c[2]), "+f"(c[3])
        : "r"(a[0]), "r"(a[1]), "r"(a[2]), "r"(a[3]), "r"(b[0]), "r"(b[1]));
}

__device__ __forceinline__ uint2 pack4half(float a, float b, float c, float d) {
    __half2 lo = __halves2half2(__float2half(a), __float2half(b));
    __half2 hi = __halves2half2(__float2half(c), __float2half(d));
    uint2 r;
    r.x = *reinterpret_cast<uint32_t*>(&lo);
    r.y = *reinterpret_cast<uint32_t*>(&hi);
    return r;
}

// ------------------- prep kernels -------------------

// x -> fp16, 4 elems / thread
__global__ void split_x_kernel(const float* __restrict__ src) {
    size_t i = ((size_t)blockIdx.x * blockDim.x + threadIdx.x) * 4;
    float4 v = *reinterpret_cast<const float4*>(src + i);
    *reinterpret_cast<uint2*>(g_x + i) = pack4half(v.x, v.y, v.z, v.w);
}

// D matrix [HD, P] -> concat A plane at column offset colbase, 4 elems / thread
__global__ void splitcat_kernel(const float* __restrict__ src, int pshift, int colbase) {
    size_t i = ((size_t)blockIdx.x * blockDim.x + threadIdx.x) * 4;
    size_t j = i >> pshift;
    int    p = (int)(i & (size_t)((1 << pshift) - 1));
    float4 v = *reinterpret_cast<const float4*>(src + i);
    *reinterpret_cast<uint2*>(g_A + j * KTOT + colbase + p) =
        pack4half(v.x, v.y, v.z, v.w);
}

// transpose + block-scale ALL W matrices into B [HD, KTOT].
// Block (32,8) handles 32 n-rows x 64 p-cols; each lane writes __half2 so a
// warp stores 128 B contiguous.
__global__ void wtrans_all_kernel(const float* __restrict__ w_qkv, const float* __restrict__ s_qkv,
                                  const float* __restrict__ w_z,   const float* __restrict__ s_z,
                                  const float* __restrict__ w_b,   const float* __restrict__ s_b,
                                  const float* __restrict__ w_a,   const float* __restrict__ s_a) {
    __shared__ float t[64][33];
    int n0  = blockIdx.x * 32;         // HD index
    int gp0 = blockIdx.y * 64;         // global concat-K index

    const float* W; const float* S; int lp0;
    if      (gp0 < 8192)  { W = w_qkv; S = s_qkv; lp0 = gp0;         }
    else if (gp0 < 12288) { W = w_z;   S = s_z;   lp0 = gp0 - 8192;  }
    else if (gp0 < 13312) { W = w_b;   S = s_b;   lp0 = gp0 - 12288; }
    else                  { W = w_a;   S = s_a;   lp0 = gp0 - 13312; }

    int tx = threadIdx.x, ty = threadIdx.y;       // block (32, 8)
    float sc = S[(lp0 >> 7) * (HD >> 7) + (n0 >> 7)];

    // load 64 p-rows x 32 n-cols (coalesced 128B per warp)
    #pragma unroll
    for (int r = 0; r < 8; ++r)
        t[ty + r * 8][tx] = W[(size_t)(lp0 + ty + r * 8) * HD + n0 + tx];
    __syncthreads();

    // write 32 n-rows x 64 p-cols; lane tx covers p = 2tx, 2tx+1
    #pragma unroll
    for (int r = 0; r < 4; ++r) {
        int nl = ty + r * 8;
        float v0 = t[2 * tx]     [nl] * sc;
        float v1 = t[2 * tx + 1] [nl] * sc;
        __half2 h = __halves2half2(__float2half(v0), __float2half(v1));
        *reinterpret_cast<__half2*>(g_B + (size_t)(n0 + nl) * KTOT + gp0 + 2 * tx) = h;
    }
}

// ------------------- main GEMM (single fp16 product, 128x256 CTA tile) -------------------
// mode 0:  M = A . B^T over K=KTOT, write fp16 g_M
// mode 1:  h = x . M^T over K=HD,   write fp32 g_h
__global__ void __launch_bounds__(256, 1) gemm_kernel(int mode) {
    const __half *A, *B;
    int K;
    if (mode == 0) { A = g_A; B = g_B; K = KTOT; }
    else           { A = g_x; B = g_M; K = HD;   }

    extern __shared__ __align__(1024) char smem[];
    const uint32_t sb = smem_u32(smem);

    const int tid = threadIdx.x;
    const int wid = tid >> 5;
    const int lid = tid & 31;
    const int m0 = blockIdx.y * 128;   // output rows  (A rows)
    const int n0 = blockIdx.x * 256;   // output cols  (B rows)
    const int wm = (wid & 1) * 64;     // warp row offset in tile
    const int wn = (wid >> 1) * 64;    // warp col offset in tile

    const int NC = K / CHUNK_K;

    // ---- chunk loader: 12 x cp.async(16B) per thread ----
    auto load_chunk = [&](int c, int s) {
        const int k0 = c * CHUNK_K;
        const uint32_t stage = sb + s * STAGE_B;
        // A tile: 128 rows x 128 B
        #pragma unroll
        for (int i = 0; i < 4; ++i) {
            int idx = tid + i * 256;           // 0..1023
            int row = idx >> 3;                // 0..127
            int seg = idx & 7;
            uint32_t sw = SWZ128((uint32_t)(row * 128 + seg * 16));
            cp_async16(stage + sw, A + (size_t)(m0 + row) * K + k0 + seg * 8);
        }
        // B tile: 256 rows x 128 B
        #pragma unroll
        for (int i = 0; i < 8; ++i) {
            int idx = tid + i * 256;           // 0..2047
            int row = idx >> 3;                // 0..255
            int seg = idx & 7;
            uint32_t sw = SWZ128((uint32_t)(row * 128 + seg * 16));
            cp_async16(stage + TILE_A_B + sw, B + (size_t)(n0 + row) * K + k0 + seg * 8);
        }
        asm volatile("cp.async.commit_group;" ::: "memory");
    };

    // prologue: stages 0, 1
    load_chunk(0, 0);
    load_chunk(1, 1);

    float acc[4][8][4];
    #pragma unroll
    for (int i = 0; i < 4; ++i)
        #pragma unroll
        for (int j = 0; j < 8; ++j)
            #pragma unroll
            for (int q = 0; q < 4; ++q) acc[i][j][q] = 0.f;

    // ldmatrix address pattern bits (per lane)
    const int lrow = lid & 7;          // row within 8x8 matrix
    const int lmat = lid >> 3;         // which of the 4 matrices

    for (int c = 0; c < NC; ++c) {
        if (c == NC - 1) asm volatile("cp.async.wait_group 0;" ::: "memory");
        else             asm volatile("cp.async.wait_group 1;" ::: "memory");
        __syncthreads();

        // issue next prefetch EARLY: stage (c+2)%3 became free at this barrier,
        // so its loads overlap the whole chunk-c compute below.
        if (c + 2 < NC) load_chunk(c + 2, (c + 2) % STAGES);

        const uint32_t stage = sb + (c % STAGES) * STAGE_B;
        const uint32_t tA = stage;
        const uint32_t tB = stage + TILE_A_B;

        #pragma unroll
        for (int ks = 0; ks < 4; ++ks) {
            const int kb = ks * 32;    // byte offset of this k16 step

            // B fragments: 4 x ldsm.x4 covers 8 n-tiles (64 cols)
            uint32_t bf[8][2];
            #pragma unroll
            for (int jp = 0; jp < 4; ++jp) {
                int brow = wn + jp * 16 + ((lmat >> 1) ? 8 : 0) + lrow;
                int bcol = kb + ((lmat & 1) ? 16 : 0);
                uint32_t r[4];
                ldsm4(r, tB + SWZ128((uint32_t)(brow * 128 + bcol)));
                bf[jp * 2 + 0][0] = r[0]; bf[jp * 2 + 0][1] = r[1];
                bf[jp * 2 + 1][0] = r[2]; bf[jp * 2 + 1][1] = r[3];
            }

            // A fragments: 4 x ldsm.x4 covers 64 rows
            uint32_t af[4][4];
            #pragma unroll
            for (int i = 0; i < 4; ++i) {
                int arow = wm + i * 16 + ((lmat & 1) ? 8 : 0) + lrow;
                int acol = kb + ((lmat & 2) ? 16 : 0);
                ldsm4(af[i], tA + SWZ128((uint32_t)(arow * 128 + acol)));
            }

            #pragma unroll
            for (int i = 0; i < 4; ++i)
                #pragma unroll
                for (int j = 0; j < 8; ++j)
                    mma_fp16(acc[i][j], af[i], bf[j]);
        }
    }

    // ---- epilogue: write accumulators ----
    const int g = lid >> 2;            // row group in fragment
    const int t4 = lid & 3;            // col pair
    #pragma unroll
    for (int i = 0; i < 4; ++i) {
        #pragma unroll
        for (int j = 0; j < 8; ++j) {
            int row = m0 + wm + i * 16 + g;
            int col = n0 + wn + j * 8 + 2 * t4;
            if (mode == 1) {
                float2 v0 = make_float2(acc[i][j][0], acc[i][j][1]);
                float2 v1 = make_float2(acc[i][j][2], acc[i][j][3]);
                *reinterpret_cast<float2*>(g_h + (size_t)row * HD + col) = v0;
                *reinterpret_cast<float2*>(g_h + (size_t)(row + 8) * HD + col) = v1;
            } else {
                __half2 v0 = __halves2half2(__float2half(acc[i][j][0]),
                                            __float2half(acc[i][j][1]));
                __half2 v1 = __halves2half2(__float2half(acc[i][j][2]),
                                            __float2half(acc[i][j][3]));
                *reinterpret_cast<__half2*>(g_M + (size_t)row * HD + col) = v0;
                *reinterpret_cast<__half2*>(g_M + (size_t)(row + 8) * HD + col) = v1;
            }
        }
    }
}

// ------------------- LayerNorm -------------------
__global__ void ln_kernel(const float* __restrict__ gamma, const float* __restrict__ beta,
                          float* __restrict__ out) {
    const int r = blockIdx.x;
    const int tid = threadIdx.x;      // 256 threads, 8 floats each
    const float* row = g_h + (size_t)r * HD;
    float4 a = *reinterpret_cast<const float4*>(row + tid * 4);
    float4 b = *reinterpret_cast<const float4*>(row + 1024 + tid * 4);
    float s = a.x + a.y + a.z + a.w + b.x + b.y + b.z + b.w;
    float q = a.x * a.x + a.y * a.y + a.z * a.z + a.w * a.w
            + b.x * b.x + b.y * b.y + b.z * b.z + b.w * b.w;
    #pragma unroll
    for (int o = 16; o; o >>= 1) {
        s += __shfl_xor_sync(0xFFFFFFFFu, s, o);
        q += __shfl_xor_sync(0xFFFFFFFFu, q, o);
    }
    __shared__ float ss[8], qq[8];
    __shared__ float mu_s, ri_s;
    if ((tid & 31) == 0) { ss[tid >> 5] = s; qq[tid >> 5] = q; }
    __syncthreads();
    if (tid == 0) {
        float S = 0.f, Q = 0.f;
        #pragma unroll
        for (int i = 0; i < 8; ++i) { S += ss[i]; Q += qq[i]; }
        float mu = S / (float)HD;
        float var = Q / (float)HD - mu * mu;
        mu_s = mu;
        ri_s = rsqrtf(var + LN_EPS);
    }
    __syncthreads();
    const float mu = mu_s, ri = ri_s;
    float4 g1 = *reinterpret_cast<const float4*>(gamma + tid * 4);
    float4 b1 = *reinterpret_cast<const float4*>(beta + tid * 4);
    float4 g2 = *reinterpret_cast<const float4*>(gamma + 1024 + tid * 4);
    float4 b2 = *reinterpret_cast<const float4*>(beta + 1024 + tid * 4);
    float4 o1, o2;
    o1.x = (a.x - mu) * ri * g1.x + b1.x;
    o1.y = (a.y - mu) * ri * g1.y + b1.y;
    o1.z = (a.z - mu) * ri * g1.z + b1.z;
    o1.w = (a.w - mu) * ri * g1.w + b1.w;
    o2.x = (b.x - mu) * ri * g2.x + b2.x;
    o2.y = (b.y - mu) * ri * g2.y + b2.y;
    o2.z = (b.z - mu) * ri * g2.z + b2.z;
    o2.w = (b.w - mu) * ri * g2.w + b2.w;
    float* orow = out + (size_t)r * HD;
    *reinterpret_cast<float4*>(orow + tid * 4) = o1;
    *reinterpret_cast<float4*>(orow + 1024 + tid * 4) = o2;
}

// ------------------- launch -------------------
extern "C" void kernel_launch(void* const* d_in, const int* in_sizes, int n_in,
                              void* d_out, int out_size) {
    const float* x     = (const float*)d_in[0];
    const float* w_qkv = (const float*)d_in[1];
    const float* s_qkv = (const float*)d_in[2];
    const float* w_z   = (const float*)d_in[3];
    const float* s_z   = (const float*)d_in[4];
    const float* w_b   = (const float*)d_in[5];
    const float* s_b   = (const float*)d_in[6];
    const float* w_a   = (const float*)d_in[7];
    const float* s_a   = (const float*)d_in[8];
    const float* d_qkv = (const float*)d_in[9];
    const float* d_z   = (const float*)d_in[10];
    const float* d_b   = (const float*)d_in[11];
    const float* d_a   = (const float*)d_in[12];
    const float* gamma = (const float*)d_in[13];
    const float* beta  = (const float*)d_in[14];
    float* out = (float*)d_out;

    cudaFuncSetAttribute(gemm_kernel, cudaFuncAttributeMaxDynamicSharedMemorySize, SMEM_REQ);

    // launches 1-4: concat D matrices into A (col bases: 0, 8192, 12288, 13312)
    splitcat_kernel<<<(HD * 8192) / 1024, 256>>>(d_qkv, 13, 0);
    splitcat_kernel<<<(HD * 4096) / 1024, 256>>>(d_z,   12, 8192);
    splitcat_kernel<<<(HD * 1024) / 1024, 256>>>(d_b,   10, 12288);
    splitcat_kernel<<<(HD * 1024) / 1024, 256>>>(d_a,   10, 13312);

    // launch 5: transpose + scale all W matrices into B (single launch)
    wtrans_all_kernel<<<dim3(HD / 32, KTOT / 64), dim3(32, 8)>>>(
        w_qkv, s_qkv, w_z, s_z, w_b, s_b, w_a, s_a);

    // launch 6: GEMM1  M = A . B^T (K = 14336), 128 CTAs = one wave
    gemm_kernel<<<dim3(HD / 256, HD / 128), 256, SMEM_REQ>>>(0);

    // launch 7: x -> fp16 (only needed by GEMM2)
    split_x_kernel<<<(NR * HD) / 1024, 256>>>(x);

    // launch 8: GEMM2  h = x . M^T (K = 2048)
    gemm_kernel<<<dim3(HD / 256, NR / 128), 256, SMEM_REQ>>>(1);

    // launch 9: LayerNorm
    ln_kernel<<<NR, 256>>>(gamma, beta, out);
}

// round 16
// speedup vs baseline: 2.5058x; 1.0411x over previous
#include <cuda_runtime.h>
#include <cuda_fp16.h>
#include <cstdint>
#include <cstddef>

// ------------------- problem constants -------------------
#define HD    2048        // hidden dim H
#define KTOT  14336       // 8192 + 4096 + 1024 + 1024
#define NR    8192        // rows of x / output
#define LN_EPS 1e-5f

// ------------------- GEMM tiling -------------------
// CTA tile 128 (M) x 256 (N), warp tile 64x64, 8 warps.
// K-chunk 128 stored as TWO 64-col sub-tiles (128 B rows, SW128 per sub-tile).
#define STAGES      2
#define CHUNK_K     128
#define SUB_A_B     (128 * 128)               // A sub-tile: 16 KB
#define SUB_B_B     (256 * 128)               // B sub-tile: 32 KB
#define TILE_A_B    (2 * SUB_A_B)             // 32 KB
#define TILE_B_B    (2 * SUB_B_B)             // 64 KB
#define STAGE_B     (TILE_A_B + TILE_B_B)     // 96 KB
#define SMEM_REQ    (STAGES * STAGE_B)        // 192 KB

#define SWZ128(off) ((off) ^ (((off) >> 3) & 0x70))

// ------------------- device scratch (no allocs allowed) -------------------
__device__ __half g_A [(size_t)HD * KTOT];   // concat D (fp16)       [2048 x 14336]
__device__ __half g_B [(size_t)HD * KTOT];   // (W*scale)^T (fp16)    [2048 x 14336]
__device__ __half g_x [(size_t)NR * HD];     // x (fp16)              [8192 x 2048]
__device__ __half g_M [(size_t)HD * HD];     // M (fp16)              [2048 x 2048]
__device__ float  g_h [(size_t)NR * HD];     // pre-LN activations

// ------------------- PTX helpers -------------------
__device__ __forceinline__ uint32_t smem_u32(const void* p) {
    uint32_t a;
    asm("{ .reg .u64 t; cvta.to.shared.u64 t, %1; cvt.u32.u64 %0, t; }" : "=r"(a) : "l"(p));
    return a;
}

__device__ __forceinline__ void cp_async16(uint32_t saddr, const void* gaddr) {
    asm volatile("cp.async.cg.shared.global [%0], [%1], 16;" :: "r"(saddr), "l"(gaddr));
}

__device__ __forceinline__ void ldsm4(uint32_t* r, uint32_t addr) {
    asm volatile("ldmatrix.sync.aligned.m8n8.x4.shared.b16 {%0,%1,%2,%3}, [%4];"
                 : "=r"(r[0]), "=r"(r[1]), "=r"(r[2]), "=r"(r[3]) : "r"(addr));
}

__device__ __forceinline__ void mma_fp16(float* c, const uint32_t* a, const uint32_t* b) {
    asm volatile(
        "mma.sync.aligned.m16n8k16.row.col.f32.f16.f16.f32 "
        "{%0,%1,%2,%3}, {%4,%5,%6,%7}, {%8,%9}, {%0,%1,%2,%3};"
        : "+f"(c[0]), "+f"(c[1]), "+f"(c[2]), "+f"(c[3])
        : "r"(a[0]), "r"(a[1]), "r"(a[2]), "r"(a[3]), "r"(b[0]), "r"(b[1]));
}

__device__ __forceinline__ uint2 pack4half(float a, float b, float c, float d) {
    __half2 lo = __halves2half2(__float2half(a), __float2half(b));
    __half2 hi = __halves2half2(__float2half(c), __float2half(d));
    uint2 r;
    r.x = *reinterpret_cast<uint32_t*>(&lo);
    r.y = *reinterpret_cast<uint32_t*>(&hi);
    return r;
}

// ------------------- prep kernels -------------------

// x -> fp16, 8 elems / thread (16B store)
__global__ void split_x_kernel(const float* __restrict__ src) {
    size_t i = ((size_t)blockIdx.x * blockDim.x + threadIdx.x) * 8;
    float4 v0 = *reinterpret_cast<const float4*>(src + i);
    float4 v1 = *reinterpret_cast<const float4*>(src + i + 4);
    uint4 o;
    uint2 a = pack4half(v0.x, v0.y, v0.z, v0.w);
    uint2 b = pack4half(v1.x, v1.y, v1.z, v1.w);
    o.x = a.x; o.y = a.y; o.z = b.x; o.w = b.y;
    *reinterpret_cast<uint4*>(g_x + i) = o;
}

// D matrix [HD, P] -> concat A plane at column offset colbase, 8 elems / thread
__global__ void splitcat_kernel(const float* __restrict__ src, int pshift, int colbase) {
    size_t i = ((size_t)blockIdx.x * blockDim.x + threadIdx.x) * 8;
    size_t j = i >> pshift;
    int    p = (int)(i & (size_t)((1 << pshift) - 1));
    float4 v0 = *reinterpret_cast<const float4*>(src + i);
    float4 v1 = *reinterpret_cast<const float4*>(src + i + 4);
    uint4 o;
    uint2 a = pack4half(v0.x, v0.y, v0.z, v0.w);
    uint2 b = pack4half(v1.x, v1.y, v1.z, v1.w);
    o.x = a.x; o.y = a.y; o.z = b.x; o.w = b.y;
    *reinterpret_cast<uint4*>(g_A + j * KTOT + colbase + p) = o;
}

// transpose + block-scale ALL W matrices into B [HD, KTOT].
// Block (32,8): 32 n-rows x 128 p-cols; each lane writes 4 halves (8B) so a
// warp stores 256 B contiguous.
__global__ void wtrans_all_kernel(const float* __restrict__ w_qkv, const float* __restrict__ s_qkv,
                                  const float* __restrict__ w_z,   const float* __restrict__ s_z,
                                  const float* __restrict__ w_b,   const float* __restrict__ s_b,
                                  const float* __restrict__ w_a,   const float* __restrict__ s_a) {
    __shared__ float t[128][33];
    int n0  = blockIdx.x * 32;         // HD index
    int gp0 = blockIdx.y * 128;        // global concat-K index (128-aligned)

    const float* W; const float* S; int lp0;
    if      (gp0 < 8192)  { W = w_qkv; S = s_qkv; lp0 = gp0;         }
    else if (gp0 < 12288) { W = w_z;   S = s_z;   lp0 = gp0 - 8192;  }
    else if (gp0 < 13312) { W = w_b;   S = s_b;   lp0 = gp0 - 12288; }
    else                  { W = w_a;   S = s_a;   lp0 = gp0 - 13312; }

    int tx = threadIdx.x, ty = threadIdx.y;       // block (32, 8)
    float sc = S[(lp0 >> 7) * (HD >> 7) + (n0 >> 7)];

    // load 128 p-rows x 32 n-cols (coalesced 128B per warp)
    #pragma unroll
    for (int r = 0; r < 16; ++r)
        t[ty + r * 8][tx] = W[(size_t)(lp0 + ty + r * 8) * HD + n0 + tx];
    __syncthreads();

    // write 32 n-rows x 128 p-cols; lane tx covers p = 4tx..4tx+3
    #pragma unroll
    for (int r = 0; r < 4; ++r) {
        int nl = ty + r * 8;
        float v0 = t[4 * tx]     [nl] * sc;
        float v1 = t[4 * tx + 1] [nl] * sc;
        float v2 = t[4 * tx + 2] [nl] * sc;
        float v3 = t[4 * tx + 3] [nl] * sc;
        *reinterpret_cast<uint2*>(g_B + (size_t)(n0 + nl) * KTOT + gp0 + 4 * tx) =
            pack4half(v0, v1, v2, v3);
    }
}

// ------------------- main GEMM (single fp16 product, 128x256 CTA, K-chunk 128) -------------------
// mode 0:  M = A . B^T over K=KTOT, write fp16 g_M
// mode 1:  h = x . M^T over K=HD,   write fp32 g_h
__global__ void __launch_bounds__(256, 1) gemm_kernel(int mode) {
    const __half *A, *B;
    int K;
    if (mode == 0) { A = g_A; B = g_B; K = KTOT; }
    else           { A = g_x; B = g_M; K = HD;   }

    extern __shared__ __align__(1024) char smem[];
    const uint32_t sb = smem_u32(smem);

    const int tid = threadIdx.x;
    const int wid = tid >> 5;
    const int lid = tid & 31;
    const int m0 = blockIdx.y * 128;   // output rows  (A rows)
    const int n0 = blockIdx.x * 256;   // output cols  (B rows)
    const int wm = (wid & 1) * 64;     // warp row offset in tile
    const int wn = (wid >> 1) * 64;    // warp col offset in tile

    const int NC = K / CHUNK_K;

    // ---- chunk loader: 24 x cp.async(16B) per thread (2 sub-tiles) ----
    auto load_chunk = [&](int c, int s) {
        const uint32_t stage = sb + s * STAGE_B;
        #pragma unroll
        for (int s2 = 0; s2 < 2; ++s2) {
            const int k0 = c * CHUNK_K + s2 * 64;
            const uint32_t aBase = stage + s2 * SUB_A_B;
            const uint32_t bBase = stage + TILE_A_B + s2 * SUB_B_B;
            // A sub-tile: 128 rows x 128 B
            #pragma unroll
            for (int i = 0; i < 4; ++i) {
                int idx = tid + i * 256;           // 0..1023
                int row = idx >> 3;
                int seg = idx & 7;
                uint32_t sw = SWZ128((uint32_t)(row * 128 + seg * 16));
                cp_async16(aBase + sw, A + (size_t)(m0 + row) * K + k0 + seg * 8);
            }
            // B sub-tile: 256 rows x 128 B
            #pragma unroll
            for (int i = 0; i < 8; ++i) {
                int idx = tid + i * 256;           // 0..2047
                int row = idx >> 3;
                int seg = idx & 7;
                uint32_t sw = SWZ128((uint32_t)(row * 128 + seg * 16));
                cp_async16(bBase + sw, B + (size_t)(n0 + row) * K + k0 + seg * 8);
            }
        }
        asm volatile("cp.async.commit_group;" ::: "memory");
    };

    // prologue
    load_chunk(0, 0);

    float acc[4][8][4];
    #pragma unroll
    for (int i = 0; i < 4; ++i)
        #pragma unroll
        for (int j = 0; j < 8; ++j)
            #pragma unroll
            for (int q = 0; q < 4; ++q) acc[i][j][q] = 0.f;

    // ldmatrix address pattern bits (per lane)
    const int lrow = lid & 7;          // row within 8x8 matrix
    const int lmat = lid >> 3;         // which of the 4 matrices

    for (int c = 0; c < NC; ++c) {
        asm volatile("cp.async.wait_group 0;" ::: "memory");
        __syncthreads();   // chunk c landed; chunk c-1 compute fully retired

        // prefetch c+1 into the other stage (its readers finished at the sync);
        // these cp.async proceed in the background during chunk-c compute.
        if (c + 1 < NC) load_chunk(c + 1, (c + 1) & 1);

        const uint32_t stage = sb + (c & 1) * STAGE_B;

        #pragma unroll
        for (int s2 = 0; s2 < 2; ++s2) {
            const uint32_t tA = stage + s2 * SUB_A_B;
            const uint32_t tB = stage + TILE_A_B + s2 * SUB_B_B;

            #pragma unroll
            for (int ks = 0; ks < 4; ++ks) {
                const int kb = ks * 32;    // byte offset of this k16 step

                // B fragments: 4 x ldsm.x4 covers 8 n-tiles (64 cols)
                uint32_t bf[8][2];
                #pragma unroll
                for (int jp = 0; jp < 4; ++jp) {
                    int brow = wn + jp * 16 + ((lmat >> 1) ? 8 : 0) + lrow;
                    int bcol = kb + ((lmat & 1) ? 16 : 0);
                    uint32_t r[4];
                    ldsm4(r, tB + SWZ128((uint32_t)(brow * 128 + bcol)));
                    bf[jp * 2 + 0][0] = r[0]; bf[jp * 2 + 0][1] = r[1];
                    bf[jp * 2 + 1][0] = r[2]; bf[jp * 2 + 1][1] = r[3];
                }

                // A fragments: 4 x ldsm.x4 covers 64 rows
                uint32_t af[4][4];
                #pragma unroll
                for (int i = 0; i < 4; ++i) {
                    int arow = wm + i * 16 + ((lmat & 1) ? 8 : 0) + lrow;
                    int acol = kb + ((lmat & 2) ? 16 : 0);
                    ldsm4(af[i], tA + SWZ128((uint32_t)(arow * 128 + acol)));
                }

                #pragma unroll
                for (int i = 0; i < 4; ++i)
                    #pragma unroll
                    for (int j = 0; j < 8; ++j)
                        mma_fp16(acc[i][j], af[i], bf[j]);
            }
        }
    }

    // ---- epilogue: write accumulators ----
    const int g = lid >> 2;            // row group in fragment
    const int t4 = lid & 3;            // col pair
    #pragma unroll
    for (int i = 0; i < 4; ++i) {
        #pragma unroll
        for (int j = 0; j < 8; ++j) {
            int row = m0 + wm + i * 16 + g;
            int col = n0 + wn + j * 8 + 2 * t4;
            if (mode == 1) {
                float2 v0 = make_float2(acc[i][j][0], acc[i][j][1]);
                float2 v1 = make_float2(acc[i][j][2], acc[i][j][3]);
                *reinterpret_cast<float2*>(g_h + (size_t)row * HD + col) = v0;
                *reinterpret_cast<float2*>(g_h + (size_t)(row + 8) * HD + col) = v1;
            } else {
                __half2 v0 = __halves2half2(__float2half(acc[i][j][0]),
                                            __float2half(acc[i][j][1]));
                __half2 v1 = __halves2half2(__float2half(acc[i][j][2]),
                                            __float2half(acc[i][j][3]));
                *reinterpret_cast<__half2*>(g_M + (size_t)row * HD + col) = v0;
                *reinterpret_cast<__half2*>(g_M + (size_t)(row + 8) * HD + col) = v1;
            }
        }
    }
}

// ------------------- LayerNorm -------------------
__global__ void ln_kernel(const float* __restrict__ gamma, const float* __restrict__ beta,
                          float* __restrict__ out) {
    const int r = blockIdx.x;
    const int tid = threadIdx.x;      // 256 threads, 8 floats each
    const float* row = g_h + (size_t)r * HD;
    float4 a = *reinterpret_cast<const float4*>(row + tid * 4);
    float4 b = *reinterpret_cast<const float4*>(row + 1024 + tid * 4);
    float s = a.x + a.y + a.z + a.w + b.x + b.y + b.z + b.w;
    float q = a.x * a.x + a.y * a.y + a.z * a.z + a.w * a.w
            + b.x * b.x + b.y * b.y + b.z * b.z + b.w * b.w;
    #pragma unroll
    for (int o = 16; o; o >>= 1) {
        s += __shfl_xor_sync(0xFFFFFFFFu, s, o);
        q += __shfl_xor_sync(0xFFFFFFFFu, q, o);
    }
    __shared__ float ss[8], qq[8];
    __shared__ float mu_s, ri_s;
    if ((tid & 31) == 0) { ss[tid >> 5] = s; qq[tid >> 5] = q; }
    __syncthreads();
    if (tid == 0) {
        float S = 0.f, Q = 0.f;
        #pragma unroll
        for (int i = 0; i < 8; ++i) { S += ss[i]; Q += qq[i]; }
        float mu = S / (float)HD;
        float var = Q / (float)HD - mu * mu;
        mu_s = mu;
        ri_s = rsqrtf(var + LN_EPS);
    }
    __syncthreads();
    const float mu = mu_s, ri = ri_s;
    float4 g1 = *reinterpret_cast<const float4*>(gamma + tid * 4);
    float4 b1 = *reinterpret_cast<const float4*>(beta + tid * 4);
    float4 g2 = *reinterpret_cast<const float4*>(gamma + 1024 + tid * 4);
    float4 b2 = *reinterpret_cast<const float4*>(beta + 1024 + tid * 4);
    float4 o1, o2;
    o1.x = (a.x - mu) * ri * g1.x + b1.x;
    o1.y = (a.y - mu) * ri * g1.y + b1.y;
    o1.z = (a.z - mu) * ri * g1.z + b1.z;
    o1.w = (a.w - mu) * ri * g1.w + b1.w;
    o2.x = (b.x - mu) * ri * g2.x + b2.x;
    o2.y = (b.y - mu) * ri * g2.y + b2.y;
    o2.z = (b.z - mu) * ri * g2.z + b2.z;
    o2.w = (b.w - mu) * ri * g2.w + b2.w;
    float* orow = out + (size_t)r * HD;
    *reinterpret_cast<float4*>(orow + tid * 4) = o1;
    *reinterpret_cast<float4*>(orow + 1024 + tid * 4) = o2;
}

// ------------------- launch -------------------
extern "C" void kernel_launch(void* const* d_in, const int* in_sizes, int n_in,
                              void* d_out, int out_size) {
    const float* x     = (const float*)d_in[0];
    const float* w_qkv = (const float*)d_in[1];
    const float* s_qkv = (const float*)d_in[2];
    const float* w_z   = (const float*)d_in[3];
    const float* s_z   = (const float*)d_in[4];
    const float* w_b   = (const float*)d_in[5];
    const float* s_b   = (const float*)d_in[6];
    const float* w_a   = (const float*)d_in[7];
    const float* s_a   = (const float*)d_in[8];
    const float* d_qkv = (const float*)d_in[9];
    const float* d_z   = (const float*)d_in[10];
    const float* d_b   = (const float*)d_in[11];
    const float* d_a   = (const float*)d_in[12];
    const float* gamma = (const float*)d_in[13];
    const float* beta  = (const float*)d_in[14];
    float* out = (float*)d_out;

    cudaFuncSetAttribute(gemm_kernel, cudaFuncAttributeMaxDynamicSharedMemorySize, SMEM_REQ);

    // launches 1-4: concat D matrices into A (col bases: 0, 8192, 12288, 13312)
    splitcat_kernel<<<(HD * 8192) / 2048, 256>>>(d_qkv, 13, 0);
    splitcat_kernel<<<(HD * 4096) / 2048, 256>>>(d_z,   12, 8192);
    splitcat_kernel<<<(HD * 1024) / 2048, 256>>>(d_b,   10, 12288);
    splitcat_kernel<<<(HD * 1024) / 2048, 256>>>(d_a,   10, 13312);

    // launch 5: transpose + scale all W matrices into B (single launch)
    wtrans_all_kernel<<<dim3(HD / 32, KTOT / 128), dim3(32, 8)>>>(
        w_qkv, s_qkv, w_z, s_z, w_b, s_b, w_a, s_a);

    // launch 6: GEMM1  M = A . B^T (K = 14336), 128 CTAs = one wave
    gemm_kernel<<<dim3(HD / 256, HD / 128), 256, SMEM_REQ>>>(0);

    // launch 7: x -> fp16 (only needed by GEMM2)
    split_x_kernel<<<(NR * HD) / 2048, 256>>>(x);

    // launch 8: GEMM2  h = x . M^T (K = 2048)
    gemm_kernel<<<dim3(HD / 256, NR / 128), 256, SMEM_REQ>>>(1);

    // launch 9: LayerNorm
    ln_kernel<<<NR, 256>>>(gamma, beta, out);
}